// round 9
// baseline (speedup 1.0000x reference)
#include <cuda_runtime.h>
#include <cuda_bf16.h>
#include <cuda_fp16.h>
#include <math.h>

// Problem constants
#define BB   4
#define LL   2048
#define DD   1024
#define KK   16
#define BL   (BB*LL)        // 8192 tokens
#define NCH  32             // scan chunks
#define LC   (LL/NCH)       // 64 tokens per chunk

// ---------------------------------------------------------------------------
// Scratch (no allocation allowed -> __device__ globals)
// ---------------------------------------------------------------------------
__device__ float g_value[BL*DD];            // 32 MB
__device__ float g_ck   [BL*KK];
__device__ float g_cq   [BL*KK];
__device__ float g_S    [BB*NCH*KK*DD];     // 8 MB chunk states

// fp16 operand panels, chunk-major, swizzled (cell ^ (row&7)) layout.
__device__ uint4 g_ahi[(16*8192*128)/16];   // 16 MB (x, later normed)
__device__ uint4 g_bhi[(16*1024*128)/16];   // 2 MB  (Wv)
__device__ uint4 g_bhi2[(16*1024*128)/16];  // 2 MB  (Wo)

// ---------------------------------------------------------------------------
// PTX helpers (base sm_90/sm_80 features only — target is plain sm_100!)
// ---------------------------------------------------------------------------
__device__ __forceinline__ unsigned smem_u32(const void* p) {
    unsigned a;
    asm("{ .reg .u64 t; cvta.to.shared.u64 t, %1; cvt.u32.u64 %0, t; }" : "=r"(a) : "l"(p));
    return a;
}

#define MBAR_INIT(addr, cnt) \
    asm volatile("mbarrier.init.shared.b64 [%0], %1;" :: "r"(addr), "r"(cnt) : "memory")
#define MBAR_INVAL(addr) \
    asm volatile("mbarrier.inval.shared.b64 [%0];" :: "r"(addr) : "memory")
#define MBAR_EXPECT_TX(addr, bytes) \
    asm volatile("mbarrier.arrive.expect_tx.shared.b64 _, [%0], %1;" :: "r"(addr), "r"(bytes) : "memory")
#define MBAR_ARRIVE(addr) \
    asm volatile("mbarrier.arrive.shared.b64 _, [%0];" :: "r"(addr) : "memory")

#define MBAR_WAIT(addr, par) do {                                              \
    unsigned _m = (addr), _p = (par), _d;                                      \
    asm volatile("{\n\t.reg .pred p;\n\t"                                      \
        "mbarrier.try_wait.parity.acquire.cta.shared::cta.b64 p, [%1], %2;\n\t"\
        "selp.b32 %0, 1, 0, p;\n\t}"                                           \
        : "=r"(_d) : "r"(_m), "r"(_p) : "memory");                             \
    if (!_d) {                                                                 \
        asm volatile("{\n\t.reg .pred P1;\n\t"                                 \
            "W%=:\n\t"                                                         \
            "mbarrier.try_wait.parity.acquire.cta.shared::cta.b64 P1, [%0], %1, 0x989680;\n\t" \
            "@P1 bra.uni D%=;\n\t"                                             \
            "bra.uni W%=;\n\t"                                                 \
            "D%=:\n\t}" :: "r"(_m), "r"(_p) : "memory");                       \
    }                                                                          \
} while (0)

#define CP_BULK(dst, src, bytes, mbar) \
    asm volatile("cp.async.bulk.shared::cluster.global.mbarrier::complete_tx::bytes [%0], [%1], %2, [%3];" \
        :: "r"(dst), "l"(src), "r"(bytes), "r"(mbar) : "memory")

#define FENCE_PROXY() asm volatile("fence.proxy.async.shared::cta;" ::: "memory")

#define LDSM_X4(r0, r1, r2, r3, addr) \
    asm volatile("ldmatrix.sync.aligned.m8n8.x4.shared.b16 {%0,%1,%2,%3}, [%4];" \
        : "=r"(r0), "=r"(r1), "=r"(r2), "=r"(r3) : "r"(addr))

__device__ __forceinline__ void mma16816h(float* d, const unsigned* a, const unsigned* b) {
    asm volatile("mma.sync.aligned.m16n8k16.row.col.f32.f16.f16.f32 "
        "{%0,%1,%2,%3}, {%4,%5,%6,%7}, {%8,%9}, {%0,%1,%2,%3};"
        : "+f"(d[0]), "+f"(d[1]), "+f"(d[2]), "+f"(d[3])
        : "r"(a[0]), "r"(a[1]), "r"(a[2]), "r"(a[3]), "r"(b[0]), "r"(b[1]));
}

// pack 2 floats -> fp16x2 bits
__device__ __forceinline__ unsigned pk2h(float x, float y) {
    __half2 h = __floats2half2_rn(x, y);
    return *reinterpret_cast<unsigned*>(&h);
}

// ---------------------------------------------------------------------------
// Kernel: conv_w — W (1024x1024 fp32) -> fp16 B panel (P=0: Wv, P=1: Wo)
// ---------------------------------------------------------------------------
template<int P>
__global__ __launch_bounds__(256)
void conv_w(const float* __restrict__ src)
{
    int id = blockIdx.x * 256 + threadIdx.x;     // 0 .. 1024*128-1
    int n = id >> 7;
    int cc = id & 127;
    int c = cc >> 3, cell = cc & 7;
    int k0 = c * 64 + cell * 8;

    const float4* s = (const float4*)(src + (size_t)n * DD + k0);
    float4 a = s[0], b = s[1];

    uint4 H = make_uint4(pk2h(a.x,a.y), pk2h(a.z,a.w), pk2h(b.x,b.y), pk2h(b.z,b.w));
    size_t off16 = ((size_t)c * DD + n) * 8 + (cell ^ (n & 7));
    if (P == 0) g_bhi[off16]  = H;
    else        g_bhi2[off16] = H;
}

// ---------------------------------------------------------------------------
// Kernel: mma_gemm — C[8192x1024] = A @ W^T (+bias, optionally +X residual)
// fp16 single-product (fp32 accum). 5-stage cp.async.bulk pipeline, scoped
// mbarrier flow control, register double-buffered ldmatrix.
// CTA tile 128x128, 8 warps (2x4), warp tile 64x32 (high per-warp mma ILP).
// MODE 0: C = g_value, B = Wv panel. MODE 1: C = Cout += X, B = Wo panel.
// ---------------------------------------------------------------------------
#define TILE_B  16384                   // one 128x64 fp16 tile
#define STG     (2*TILE_B)              // A, B = 32 KB
#define KBLK    16
#define NSTAGE  5
#define GSMEM   (1024 + NSTAGE*STG)     // 164864
#define NWARP   8

template<int MODE>
__global__ __launch_bounds__(256, 1)
void mma_gemm(const float* __restrict__ bias, const float* __restrict__ X,
              float* __restrict__ Cout)
{
    extern __shared__ char smem[];
    unsigned sb = smem_u32(smem);
    int tid = threadIdx.x, lane = tid & 31, wid = tid >> 5;
    int wm = wid & 1, wn = wid >> 1;          // 2 x 4 warp grid, 64x32 tiles
    int bn = blockIdx.x * 128, bm = blockIdx.y * 128;
    float* C = (MODE == 0) ? g_value : Cout;

    // mbarriers: full[s] at sb+8+16s, cons[s] at sb+16+16s
    if (tid == 0) {
        #pragma unroll
        for (int s = 0; s < NSTAGE; ++s) {
            MBAR_INIT(sb + 8  + 16*s, 1);
            MBAR_INIT(sb + 16 + 16*s, NWARP);
        }
        FENCE_PROXY();
    }
    __syncthreads();

    const char* pA = (const char*)g_ahi;
    const char* pB = (MODE == 0) ? (const char*)g_bhi : (const char*)g_bhi2;

    auto issue = [&](int kb, int s) {
        unsigned st = sb + 1024 + s * STG;
        unsigned fm = sb + 8 + 16*s;
        size_t aoff = ((size_t)kb * BL + bm) * 128;
        size_t boff = ((size_t)kb * DD + bn) * 128;
        MBAR_EXPECT_TX(fm, STG);
        CP_BULK(st,          pA + aoff, TILE_B, fm);
        CP_BULK(st + TILE_B, pB + boff, TILE_B, fm);
    };
    if (tid == 0) {
        #pragma unroll
        for (int s = 0; s < NSTAGE - 1; ++s) issue(s, s);
    }

    float acc[4][4][4];
    #pragma unroll
    for (int i = 0; i < 4; ++i)
        #pragma unroll
        for (int j = 0; j < 4; ++j)
            #pragma unroll
            for (int q = 0; q < 4; ++q) acc[i][j][q] = 0.f;

    int rl = (lane & 7) + ((lane >> 3) & 1) * 8;
    int cs = lane >> 4;

    int rA[4], sA[4], rB[2], sB[2];
    #pragma unroll
    for (int i = 0; i < 4; ++i) { int r = wm*64 + i*16 + rl; rA[i] = r*128; sA[i] = r & 7; }
    #pragma unroll
    for (int j = 0; j < 2; ++j) { int r = wn*32 + j*16 + rl; rB[j] = r*128; sB[j] = r & 7; }

    // operand double buffers: A 16 regs, B 8 regs per buffer
    unsigned opA[2][16], opB[2][8];

    auto load_ops = [&](unsigned bA, unsigned bBp, int ks, unsigned* A, unsigned* B) {
        int cc = ks * 2 + cs;
        #pragma unroll
        for (int i = 0; i < 4; ++i) {
            unsigned off = rA[i] + ((cc ^ sA[i]) << 4);
            LDSM_X4(A[i*4+0], A[i*4+1], A[i*4+2], A[i*4+3], bA + off);
        }
        #pragma unroll
        for (int jp = 0; jp < 2; ++jp) {
            unsigned off = rB[jp] + ((cc ^ sB[jp]) << 4);
            unsigned r0, r1, r2, r3;
            LDSM_X4(r0, r1, r2, r3, bBp + off);
            B[jp*4+0] = r0; B[jp*4+1] = r2; B[jp*4+2] = r1; B[jp*4+3] = r3;
        }
    };

    auto do_mma = [&](const unsigned* A, const unsigned* B) {
        #pragma unroll
        for (int jp = 0; jp < 2; ++jp)
            #pragma unroll
            for (int i = 0; i < 4; ++i) {
                mma16816h(acc[i][jp*2+0], A + i*4, B + jp*4 + 0);
                mma16816h(acc[i][jp*2+1], A + i*4, B + jp*4 + 2);
            }
    };

    for (int kb = 0; kb < KBLK; ++kb) {
        int s  = kb % NSTAGE;
        int ph = (kb / NSTAGE) & 1;
        MBAR_WAIT(sb + 8 + 16*s, ph);
        unsigned st = sb + 1024 + s * STG;
        unsigned bA = st, bBp = st + TILE_B;

        load_ops(bA, bBp, 0, opA[0], opB[0]);
        #pragma unroll
        for (int ks = 0; ks < 4; ++ks) {
            int cur = ks & 1;
            if (ks < 3) load_ops(bA, bBp, ks + 1, opA[cur^1], opB[cur^1]);
            do_mma(opA[cur], opB[cur]);
        }

        if (lane == 0) MBAR_ARRIVE(sb + 16 + 16*s);
        if (tid == 0 && kb + NSTAGE - 1 < KBLK) {
            MBAR_WAIT(sb + 16 + 16*s, ph);
            issue(kb + NSTAGE - 1, (kb + NSTAGE - 1) % NSTAGE);
        }
    }

    // epilogue: warp writes its 64x32 sub-tile
    #pragma unroll
    for (int i = 0; i < 4; ++i) {
        int r0 = bm + wm*64 + i*16 + (lane >> 2);
        #pragma unroll
        for (int j = 0; j < 4; ++j) {
            int col = bn + wn*32 + j*8 + (lane & 3)*2;
            float2 b2 = *(const float2*)(bias + col);
            float2 v0 = make_float2(acc[i][j][0] + b2.x, acc[i][j][1] + b2.y);
            float2 v1 = make_float2(acc[i][j][2] + b2.x, acc[i][j][3] + b2.y);
            if (MODE == 1) {
                float2 x0 = *(const float2*)(X + (size_t)r0*DD + col);
                float2 x1 = *(const float2*)(X + (size_t)(r0+8)*DD + col);
                v0.x += x0.x; v0.y += x0.y;
                v1.x += x1.x; v1.y += x1.y;
            }
            *(float2*)(C + (size_t)r0*DD + col)     = v0;
            *(float2*)(C + (size_t)(r0+8)*DD + col) = v1;
        }
    }

    __syncthreads();
    if (tid == 0) {
        #pragma unroll
        for (int s = 0; s < NSTAGE; ++s) {
            MBAR_INVAL(sb + 8  + 16*s);
            MBAR_INVAL(sb + 16 + 16*s);
        }
    }
}

// ---------------------------------------------------------------------------
// Kernel: proj — content key/query + combiner for 8 tokens per block,
// FUSED with x -> fp16 A-panel conversion (reads x once).
// ---------------------------------------------------------------------------
#define PT 8
__global__ __launch_bounds__(256)
void proj_kernel(const float* __restrict__ x,
                 const float* __restrict__ Wck, const float* __restrict__ bck,
                 const float* __restrict__ Wcq, const float* __restrict__ bcq,
                 const float* __restrict__ Wc,  const float* __restrict__ bc,
                 const float* __restrict__ pos_key)
{
    int t0   = blockIdx.x * PT;
    int tid  = threadIdx.x;
    int lane = tid & 31;
    int warp = tid >> 5;

    __shared__ float xs[PT][DD];
    __shared__ float dots[2][PT][16];
    __shared__ float pos_s[PT][16];

    #pragma unroll
    for (int i = tid; i < PT*DD/4; i += 256)
        ((float4*)&xs[0][0])[i] = ((const float4*)(x + (size_t)t0*DD))[i];
    if (tid < PT*16) {
        int tt = tid >> 4, k = tid & 15;
        int l = (t0 + tt) & (LL-1);
        pos_s[tt][k] = pos_key[l*KK + k];
    }
    __syncthreads();

    // --- fused conv: emit fp16 panel rows ---
    {
        int tt   = tid >> 5;
        int t    = t0 + tt;
        int cell = lane & 7;
        #pragma unroll
        for (int q = 0; q < 4; ++q) {
            int c  = (lane >> 3) + q*4;
            int k0 = c*64 + cell*8;
            const float* v = &xs[tt][k0];
            uint4 H = make_uint4(pk2h(v[0],v[1]), pk2h(v[2],v[3]),
                                 pk2h(v[4],v[5]), pk2h(v[6],v[7]));
            size_t off16 = ((size_t)c * BL + t) * 8 + (cell ^ (t & 7));
            g_ahi[off16] = H;
        }
    }

    // --- 32 dot products; each warp does 4 (sequential — keeps regs low) ---
    #pragma unroll 1
    for (int oo = 0; oo < 4; ++oo) {
        int o = warp + oo*8;
        const float* W = (o < 16) ? (Wck + (size_t)o*DD) : (Wcq + (size_t)(o-16)*DD);
        float bias_o   = (o < 16) ? bck[o] : bcq[o-16];
        float wreg[32];
        #pragma unroll
        for (int i = 0; i < 32; ++i) wreg[i] = W[lane + 32*i];
        #pragma unroll
        for (int t = 0; t < PT; ++t) {
            float s = 0.f;
            #pragma unroll
            for (int i = 0; i < 32; ++i) s += wreg[i] * xs[t][lane + 32*i];
            #pragma unroll
            for (int off = 16; off; off >>= 1)
                s += __shfl_xor_sync(0xffffffffu, s, off);
            if (lane == 0)
                dots[o >> 4][t][o & 15] = s + bias_o;
        }
    }
    __syncthreads();

    // --- normalize + combiner + normalize ---
    {
        int t    = warp;
        int path = lane >> 4;
        int l16  = lane & 15;

        float v = dots[path][t][l16];
        float ss = v*v;
        #pragma unroll
        for (int off = 8; off; off >>= 1)
            ss += __shfl_xor_sync(0xffffffffu, ss, off, 16);
        float cnv = v / fmaxf(sqrtf(ss), 1e-12f);

        float s = bc[l16];
        #pragma unroll
        for (int j = 0; j < 16; ++j) {
            float cj = __shfl_sync(0xffffffffu, cnv, j, 16);
            s += Wc[l16*32 + j]      * pos_s[t][j];
            s += Wc[l16*32 + 16 + j] * cj;
        }
        s = tanhf(s);
        float sq = s*s;
        #pragma unroll
        for (int off = 8; off; off >>= 1)
            sq += __shfl_xor_sync(0xffffffffu, sq, off, 16);
        float outv = s / fmaxf(sqrtf(sq), 1e-12f);
        float* dst = (path == 0) ? g_ck : g_cq;
        dst[(t0 + t)*KK + l16] = outv;
    }
}

// ---------------------------------------------------------------------------
// Kernel: per-chunk partial state  S[b,c,k,d] = sum_{t in chunk} v[t,d]*ck[t,k]
// ---------------------------------------------------------------------------
__global__ __launch_bounds__(128)
void scan_partial()
{
    int d = blockIdx.x * 128 + threadIdx.x;
    int c = blockIdx.y;
    int b = blockIdx.z;
    __shared__ float cks[LC*KK];

    int base_t = b*LL + c*LC;
    for (int i = threadIdx.x; i < LC*KK; i += 128)
        cks[i] = g_ck[base_t*KK + i];
    __syncthreads();

    float st[KK];
    #pragma unroll
    for (int k = 0; k < KK; ++k) st[k] = 0.f;

    const float* vp = g_value + (size_t)base_t*DD + d;
    for (int t = 0; t < LC; ++t) {
        float v = vp[(size_t)t*DD];
        #pragma unroll
        for (int k = 0; k < KK; ++k) st[k] += v * cks[t*KK + k];
    }
    float* Sp = g_S + ((size_t)(b*NCH + c)*KK)*DD + d;
    #pragma unroll
    for (int k = 0; k < KK; ++k) Sp[(size_t)k*DD] = st[k];
}

// ---------------------------------------------------------------------------
// Kernel: exclusive prefix over chunks — batched loads for MLP
// ---------------------------------------------------------------------------
__global__ __launch_bounds__(256)
void scan_prefix()
{
    int id  = blockIdx.x * 256 + threadIdx.x;   // 0 .. B*K*D-1
    int b   = id >> 14;
    int rem = id & 16383;
    float* base = g_S + (size_t)b*NCH*KK*DD + rem;

    float v[NCH];
    #pragma unroll
    for (int c = 0; c < NCH; ++c)
        v[c] = base[(size_t)c*KK*DD];
    float run = 0.f;
    #pragma unroll
    for (int c = 0; c < NCH; ++c) {
        float t = v[c];
        base[(size_t)c*KK*DD] = run;
        run += t;
    }
}

// ---------------------------------------------------------------------------
// Kernel: scan_apply + LayerNorm + fp16 panel conversion, FUSED.
// grid (NCH, BB), 1024 threads; block owns all D columns of a 64-token chunk.
// Eliminates g_ret round-trip entirely.
// ---------------------------------------------------------------------------
__global__ __launch_bounds__(1024)
void scan_apply_ln(const float* __restrict__ gam, const float* __restrict__ bet)
{
    int d = threadIdx.x;       // 0..1023
    int c = blockIdx.x;
    int b = blockIdx.y;
    int lane = d & 31, wrp = d >> 5;

    __shared__ float cks[LC*KK];
    __shared__ float cqs[LC*KK];
    __shared__ float wsum[32], wsq[32];
    __shared__ float s_stats[2];

    int base_t = b*LL + c*LC;
    for (int i = d; i < LC*KK; i += 1024) {
        cks[i] = g_ck[base_t*KK + i];
        cqs[i] = g_cq[base_t*KK + i];
    }
    __syncthreads();

    float st[KK];
    const float* Sp = g_S + ((size_t)(b*NCH + c)*KK)*DD + d;
    #pragma unroll
    for (int k = 0; k < KK; ++k) st[k] = Sp[(size_t)k*DD];

    float gm = gam[d], bt = bet[d];
    const float* vp = g_value + (size_t)base_t*DD + d;
    float vcur = vp[0];

    int c8 = d >> 6;
    int inbase = (d & 63) * 2;

    for (int t = 0; t < LC; ++t) {
        float vnext = (t + 1 < LC) ? vp[(size_t)(t+1)*DD] : 0.f;

        float acc = 0.f;
        #pragma unroll
        for (int k = 0; k < KK; ++k) {
            st[k] += vcur * cks[t*KK + k];
            acc   += cqs[t*KK + k] * st[k];
        }
        float r = acc * 0.25f;   // 1/sqrt(16)

        // block reduction: mean & var over 1024 values
        float s1 = r, s2 = r*r;
        #pragma unroll
        for (int off = 16; off; off >>= 1) {
            s1 += __shfl_xor_sync(0xffffffffu, s1, off);
            s2 += __shfl_xor_sync(0xffffffffu, s2, off);
        }
        if (lane == 0) { wsum[wrp] = s1; wsq[wrp] = s2; }
        __syncthreads();
        if (wrp == 0) {
            float a = wsum[lane], q = wsq[lane];
            #pragma unroll
            for (int off = 16; off; off >>= 1) {
                a += __shfl_xor_sync(0xffffffffu, a, off);
                q += __shfl_xor_sync(0xffffffffu, q, off);
            }
            if (lane == 0) {
                float m = a * (1.0f/DD);
                s_stats[0] = m;
                s_stats[1] = rsqrtf(q * (1.0f/DD) - m*m + 1e-5f);
            }
        }
        __syncthreads();
        float m = s_stats[0], rstd = s_stats[1];
        float nv = (r - m) * rstd * gm + bt;

        int tt = base_t + t;
        int inrow = inbase ^ ((tt & 7) << 4);
        *(__half*)((char*)g_ahi + ((size_t)c8 * BL + tt) * 128 + inrow) = __float2half_rn(nv);

        vcur = vnext;
    }
}

// ---------------------------------------------------------------------------
extern "C" void kernel_launch(void* const* d_in, const int* in_sizes, int n_in,
                              void* d_out, int out_size)
{
    const float* x       = (const float*)d_in[0];
    const float* Wv      = (const float*)d_in[1];
    const float* bv      = (const float*)d_in[2];
    const float* Wck     = (const float*)d_in[3];
    const float* bck     = (const float*)d_in[4];
    const float* Wc      = (const float*)d_in[5];
    const float* bc      = (const float*)d_in[6];
    const float* Wcq     = (const float*)d_in[7];
    const float* bcq     = (const float*)d_in[8];
    const float* ln_g    = (const float*)d_in[9];
    const float* ln_b    = (const float*)d_in[10];
    const float* Wo      = (const float*)d_in[11];
    const float* bo      = (const float*)d_in[12];
    const float* pos_key = (const float*)d_in[13];
    float* out = (float*)d_out;

    cudaFuncSetAttribute(mma_gemm<0>, cudaFuncAttributeMaxDynamicSharedMemorySize, GSMEM);
    cudaFuncSetAttribute(mma_gemm<1>, cudaFuncAttributeMaxDynamicSharedMemorySize, GSMEM);

    // weight panels (off critical path)
    conv_w<0><<<(DD*128)/256, 256>>>(Wv);
    conv_w<1><<<(DD*128)/256, 256>>>(Wo);

    // proj + fused x->panel conversion
    proj_kernel<<<BL/PT, 256>>>(x, Wck, bck, Wcq, bcq, Wc, bc, pos_key);

    // value = x @ Wv^T + bv
    mma_gemm<0><<<dim3(DD/128, BL/128), 256, GSMEM>>>(bv, nullptr, nullptr);

    // chunked causal scan
    {
        dim3 grid(DD/128, NCH, BB);
        scan_partial<<<grid, 128>>>();
        scan_prefix<<<(BB*KK*DD)/256, 256>>>();
    }

    // scan apply + LayerNorm + fp16 panel conversion (fused)
    scan_apply_ln<<<dim3(NCH, BB), 1024>>>(ln_g, ln_b);

    // out = x + normed @ Wo^T + bo
    mma_gemm<1><<<dim3(DD/128, BL/128), 256, GSMEM>>>(bo, x, out);
}

// round 11
// speedup vs baseline: 1.1080x; 1.1080x over previous
#include <cuda_runtime.h>
#include <cuda_bf16.h>
#include <cuda_fp16.h>
#include <math.h>

// Problem constants
#define BB   4
#define LL   2048
#define DD   1024
#define KK   16
#define BL   (BB*LL)        // 8192 tokens
#define NCH  32             // scan chunks
#define LC   (LL/NCH)       // 64 tokens per chunk

// ---------------------------------------------------------------------------
// Scratch (no allocation allowed -> __device__ globals)
// ---------------------------------------------------------------------------
__device__ float g_value[BL*DD];            // 32 MB
__device__ float g_ret  [BL*DD];            // 32 MB (retrieved, pre-LN)
__device__ float g_ck   [BL*KK];
__device__ float g_cq   [BL*KK];
__device__ float g_S    [BB*NCH*KK*DD];     // 8 MB chunk states

// fp16 operand panels, chunk-major, swizzled (cell ^ (row&7)) layout.
__device__ uint4 g_ahi[(16*8192*128)/16];   // 16 MB (x, later normed)
__device__ uint4 g_bhi[(16*1024*128)/16];   // 2 MB  (Wv)
__device__ uint4 g_bhi2[(16*1024*128)/16];  // 2 MB  (Wo)

// ---------------------------------------------------------------------------
// PTX helpers (base sm_90/sm_80 features only — target is plain sm_100!)
// ---------------------------------------------------------------------------
__device__ __forceinline__ unsigned smem_u32(const void* p) {
    unsigned a;
    asm("{ .reg .u64 t; cvta.to.shared.u64 t, %1; cvt.u32.u64 %0, t; }" : "=r"(a) : "l"(p));
    return a;
}

#define MBAR_INIT(addr, cnt) \
    asm volatile("mbarrier.init.shared.b64 [%0], %1;" :: "r"(addr), "r"(cnt) : "memory")
#define MBAR_INVAL(addr) \
    asm volatile("mbarrier.inval.shared.b64 [%0];" :: "r"(addr) : "memory")
#define MBAR_EXPECT_TX(addr, bytes) \
    asm volatile("mbarrier.arrive.expect_tx.shared.b64 _, [%0], %1;" :: "r"(addr), "r"(bytes) : "memory")
#define MBAR_ARRIVE(addr) \
    asm volatile("mbarrier.arrive.shared.b64 _, [%0];" :: "r"(addr) : "memory")

#define MBAR_WAIT(addr, par) do {                                              \
    unsigned _m = (addr), _p = (par), _d;                                      \
    asm volatile("{\n\t.reg .pred p;\n\t"                                      \
        "mbarrier.try_wait.parity.acquire.cta.shared::cta.b64 p, [%1], %2;\n\t"\
        "selp.b32 %0, 1, 0, p;\n\t}"                                           \
        : "=r"(_d) : "r"(_m), "r"(_p) : "memory");                             \
    if (!_d) {                                                                 \
        asm volatile("{\n\t.reg .pred P1;\n\t"                                 \
            "W%=:\n\t"                                                         \
            "mbarrier.try_wait.parity.acquire.cta.shared::cta.b64 P1, [%0], %1, 0x989680;\n\t" \
            "@P1 bra.uni D%=;\n\t"                                             \
            "bra.uni W%=;\n\t"                                                 \
            "D%=:\n\t}" :: "r"(_m), "r"(_p) : "memory");                       \
    }                                                                          \
} while (0)

#define CP_BULK(dst, src, bytes, mbar) \
    asm volatile("cp.async.bulk.shared::cluster.global.mbarrier::complete_tx::bytes [%0], [%1], %2, [%3];" \
        :: "r"(dst), "l"(src), "r"(bytes), "r"(mbar) : "memory")

#define FENCE_PROXY() asm volatile("fence.proxy.async.shared::cta;" ::: "memory")

#define LDSM_X4(r0, r1, r2, r3, addr) \
    asm volatile("ldmatrix.sync.aligned.m8n8.x4.shared.b16 {%0,%1,%2,%3}, [%4];" \
        : "=r"(r0), "=r"(r1), "=r"(r2), "=r"(r3) : "r"(addr))

__device__ __forceinline__ void mma16816h(float* d, const unsigned* a, const unsigned* b) {
    asm volatile("mma.sync.aligned.m16n8k16.row.col.f32.f16.f16.f32 "
        "{%0,%1,%2,%3}, {%4,%5,%6,%7}, {%8,%9}, {%0,%1,%2,%3};"
        : "+f"(d[0]), "+f"(d[1]), "+f"(d[2]), "+f"(d[3])
        : "r"(a[0]), "r"(a[1]), "r"(a[2]), "r"(a[3]), "r"(b[0]), "r"(b[1]));
}

// pack 2 floats -> fp16x2 bits
__device__ __forceinline__ unsigned pk2h(float x, float y) {
    __half2 h = __floats2half2_rn(x, y);
    return *reinterpret_cast<unsigned*>(&h);
}

// ---------------------------------------------------------------------------
// Kernel: conv_w — W (1024x1024 fp32) -> fp16 B panel (P=0: Wv, P=1: Wo)
// ---------------------------------------------------------------------------
template<int P>
__global__ __launch_bounds__(256)
void conv_w(const float* __restrict__ src)
{
    int id = blockIdx.x * 256 + threadIdx.x;     // 0 .. 1024*128-1
    int n = id >> 7;
    int cc = id & 127;
    int c = cc >> 3, cell = cc & 7;
    int k0 = c * 64 + cell * 8;

    const float4* s = (const float4*)(src + (size_t)n * DD + k0);
    float4 a = s[0], b = s[1];

    uint4 H = make_uint4(pk2h(a.x,a.y), pk2h(a.z,a.w), pk2h(b.x,b.y), pk2h(b.z,b.w));
    size_t off16 = ((size_t)c * DD + n) * 8 + (cell ^ (n & 7));
    if (P == 0) g_bhi[off16]  = H;
    else        g_bhi2[off16] = H;
}

// ---------------------------------------------------------------------------
// Kernel: mma_gemm — C[8192x1024] = A @ W^T (+bias, optionally +X residual)
// fp16 single-product (fp32 accum). 4-stage cp.async.bulk pipeline, scoped
// mbarrier flow control, register double-buffered ldmatrix.
// CTA tile 128x256, 8 warps (2x4), warp tile 64x64 -> smem read redundancy 2x
// (vs 4x for 32x32 tiles) and 32-deep mma ILP per ks.
// MODE 0: C = g_value, B = Wv panel. MODE 1: C = Cout += X, B = Wo panel.
// ---------------------------------------------------------------------------
#define TILE_A   16384                  // 128x64 fp16
#define TILE_BB  32768                  // 256x64 fp16
#define STG      (TILE_A + TILE_BB)     // 48 KB
#define KBLK     16
#define NSTAGE   4
#define GSMEM    (1024 + NSTAGE*STG)    // 197632
#define NWARP    8

template<int MODE>
__global__ __launch_bounds__(256, 1)
void mma_gemm(const float* __restrict__ bias, const float* __restrict__ X,
              float* __restrict__ Cout)
{
    extern __shared__ char smem[];
    unsigned sb = smem_u32(smem);
    int tid = threadIdx.x, lane = tid & 31, wid = tid >> 5;
    int wm = wid & 1, wn = wid >> 1;          // 2 x 4 warp grid, 64x64 tiles
    int bn = blockIdx.x * 256, bm = blockIdx.y * 128;
    float* C = (MODE == 0) ? g_value : Cout;

    // mbarriers: full[s] at sb+8+16s, cons[s] at sb+16+16s
    if (tid == 0) {
        #pragma unroll
        for (int s = 0; s < NSTAGE; ++s) {
            MBAR_INIT(sb + 8  + 16*s, 1);
            MBAR_INIT(sb + 16 + 16*s, NWARP);
        }
        FENCE_PROXY();
    }
    __syncthreads();

    const char* pA = (const char*)g_ahi;
    const char* pB = (MODE == 0) ? (const char*)g_bhi : (const char*)g_bhi2;

    auto issue = [&](int kb, int s) {
        unsigned st = sb + 1024 + s * STG;
        unsigned fm = sb + 8 + 16*s;
        size_t aoff = ((size_t)kb * BL + bm) * 128;
        size_t boff = ((size_t)kb * DD + bn) * 128;
        MBAR_EXPECT_TX(fm, STG);
        CP_BULK(st,          pA + aoff, TILE_A,  fm);
        CP_BULK(st + TILE_A, pB + boff, TILE_BB, fm);
    };
    if (tid == 0) {
        #pragma unroll
        for (int s = 0; s < NSTAGE - 1; ++s) issue(s, s);
    }

    float acc[4][8][4];
    #pragma unroll
    for (int i = 0; i < 4; ++i)
        #pragma unroll
        for (int j = 0; j < 8; ++j)
            #pragma unroll
            for (int q = 0; q < 4; ++q) acc[i][j][q] = 0.f;

    int rl = (lane & 7) + ((lane >> 3) & 1) * 8;
    int cs = lane >> 4;

    int rA[4], sA[4], rB[4], sB[4];
    #pragma unroll
    for (int i = 0; i < 4; ++i) { int r = wm*64 + i*16 + rl; rA[i] = r*128; sA[i] = r & 7; }
    #pragma unroll
    for (int j = 0; j < 4; ++j) { int r = wn*64 + j*16 + rl; rB[j] = r*128; sB[j] = r & 7; }

    // operand double buffers: A 16 regs, B 16 regs per buffer
    unsigned opA[2][16], opB[2][16];

    auto load_ops = [&](unsigned bA, unsigned bBp, int ks, unsigned* A, unsigned* B) {
        int cc = ks * 2 + cs;
        #pragma unroll
        for (int i = 0; i < 4; ++i) {
            unsigned off = rA[i] + ((cc ^ sA[i]) << 4);
            LDSM_X4(A[i*4+0], A[i*4+1], A[i*4+2], A[i*4+3], bA + off);
        }
        #pragma unroll
        for (int j = 0; j < 4; ++j) {
            unsigned off = rB[j] + ((cc ^ sB[j]) << 4);
            unsigned r0, r1, r2, r3;
            LDSM_X4(r0, r1, r2, r3, bBp + off);
            B[j*4+0] = r0; B[j*4+1] = r2; B[j*4+2] = r1; B[j*4+3] = r3;
        }
    };

    auto do_mma = [&](const unsigned* A, const unsigned* B) {
        #pragma unroll
        for (int jt = 0; jt < 4; ++jt)
            #pragma unroll
            for (int h = 0; h < 2; ++h) {
                const unsigned* Bf = B + jt*4 + h*2;
                #pragma unroll
                for (int i = 0; i < 4; ++i)
                    mma16816h(acc[i][jt*2+h], A + i*4, Bf);
            }
    };

    for (int kb = 0; kb < KBLK; ++kb) {
        int s  = kb % NSTAGE;
        int ph = (kb / NSTAGE) & 1;
        MBAR_WAIT(sb + 8 + 16*s, ph);
        unsigned st = sb + 1024 + s * STG;
        unsigned bA = st, bBp = st + TILE_A;

        load_ops(bA, bBp, 0, opA[0], opB[0]);
        #pragma unroll
        for (int ks = 0; ks < 4; ++ks) {
            int cur = ks & 1;
            if (ks < 3) load_ops(bA, bBp, ks + 1, opA[cur^1], opB[cur^1]);
            do_mma(opA[cur], opB[cur]);
        }

        if (lane == 0) MBAR_ARRIVE(sb + 16 + 16*s);
        if (tid == 0 && kb + NSTAGE - 1 < KBLK) {
            MBAR_WAIT(sb + 16 + 16*s, ph);
            issue(kb + NSTAGE - 1, (kb + NSTAGE - 1) % NSTAGE);
        }
    }

    // epilogue: warp writes its 64x64 sub-tile
    #pragma unroll
    for (int i = 0; i < 4; ++i) {
        int r0 = bm + wm*64 + i*16 + (lane >> 2);
        #pragma unroll
        for (int j = 0; j < 8; ++j) {
            int col = bn + wn*64 + j*8 + (lane & 3)*2;
            float2 b2 = *(const float2*)(bias + col);
            float2 v0 = make_float2(acc[i][j][0] + b2.x, acc[i][j][1] + b2.y);
            float2 v1 = make_float2(acc[i][j][2] + b2.x, acc[i][j][3] + b2.y);
            if (MODE == 1) {
                float2 x0 = *(const float2*)(X + (size_t)r0*DD + col);
                float2 x1 = *(const float2*)(X + (size_t)(r0+8)*DD + col);
                v0.x += x0.x; v0.y += x0.y;
                v1.x += x1.x; v1.y += x1.y;
            }
            *(float2*)(C + (size_t)r0*DD + col)     = v0;
            *(float2*)(C + (size_t)(r0+8)*DD + col) = v1;
        }
    }

    __syncthreads();
    if (tid == 0) {
        #pragma unroll
        for (int s = 0; s < NSTAGE; ++s) {
            MBAR_INVAL(sb + 8  + 16*s);
            MBAR_INVAL(sb + 16 + 16*s);
        }
    }
}

// ---------------------------------------------------------------------------
// Kernel: proj — content key/query + combiner for 8 tokens per block,
// FUSED with x -> fp16 A-panel conversion (reads x once).
// ---------------------------------------------------------------------------
#define PT 8
__global__ __launch_bounds__(256)
void proj_kernel(const float* __restrict__ x,
                 const float* __restrict__ Wck, const float* __restrict__ bck,
                 const float* __restrict__ Wcq, const float* __restrict__ bcq,
                 const float* __restrict__ Wc,  const float* __restrict__ bc,
                 const float* __restrict__ pos_key)
{
    int t0   = blockIdx.x * PT;
    int tid  = threadIdx.x;
    int lane = tid & 31;
    int warp = tid >> 5;

    __shared__ float xs[PT][DD];
    __shared__ float dots[2][PT][16];
    __shared__ float pos_s[PT][16];

    #pragma unroll
    for (int i = tid; i < PT*DD/4; i += 256)
        ((float4*)&xs[0][0])[i] = ((const float4*)(x + (size_t)t0*DD))[i];
    if (tid < PT*16) {
        int tt = tid >> 4, k = tid & 15;
        int l = (t0 + tt) & (LL-1);
        pos_s[tt][k] = pos_key[l*KK + k];
    }
    __syncthreads();

    // --- fused conv: emit fp16 panel rows ---
    {
        int tt   = tid >> 5;
        int t    = t0 + tt;
        int cell = lane & 7;
        #pragma unroll
        for (int q = 0; q < 4; ++q) {
            int c  = (lane >> 3) + q*4;
            int k0 = c*64 + cell*8;
            const float* v = &xs[tt][k0];
            uint4 H = make_uint4(pk2h(v[0],v[1]), pk2h(v[2],v[3]),
                                 pk2h(v[4],v[5]), pk2h(v[6],v[7]));
            size_t off16 = ((size_t)c * BL + t) * 8 + (cell ^ (t & 7));
            g_ahi[off16] = H;
        }
    }

    // --- 32 dot products; each warp does 4 (sequential — keeps regs low) ---
    #pragma unroll 1
    for (int oo = 0; oo < 4; ++oo) {
        int o = warp + oo*8;
        const float* W = (o < 16) ? (Wck + (size_t)o*DD) : (Wcq + (size_t)(o-16)*DD);
        float bias_o   = (o < 16) ? bck[o] : bcq[o-16];
        float wreg[32];
        #pragma unroll
        for (int i = 0; i < 32; ++i) wreg[i] = W[lane + 32*i];
        #pragma unroll
        for (int t = 0; t < PT; ++t) {
            float s = 0.f;
            #pragma unroll
            for (int i = 0; i < 32; ++i) s += wreg[i] * xs[t][lane + 32*i];
            #pragma unroll
            for (int off = 16; off; off >>= 1)
                s += __shfl_xor_sync(0xffffffffu, s, off);
            if (lane == 0)
                dots[o >> 4][t][o & 15] = s + bias_o;
        }
    }
    __syncthreads();

    // --- normalize + combiner + normalize ---
    {
        int t    = warp;
        int path = lane >> 4;
        int l16  = lane & 15;

        float v = dots[path][t][l16];
        float ss = v*v;
        #pragma unroll
        for (int off = 8; off; off >>= 1)
            ss += __shfl_xor_sync(0xffffffffu, ss, off, 16);
        float cnv = v / fmaxf(sqrtf(ss), 1e-12f);

        float s = bc[l16];
        #pragma unroll
        for (int j = 0; j < 16; ++j) {
            float cj = __shfl_sync(0xffffffffu, cnv, j, 16);
            s += Wc[l16*32 + j]      * pos_s[t][j];
            s += Wc[l16*32 + 16 + j] * cj;
        }
        s = tanhf(s);
        float sq = s*s;
        #pragma unroll
        for (int off = 8; off; off >>= 1)
            sq += __shfl_xor_sync(0xffffffffu, sq, off, 16);
        float outv = s / fmaxf(sqrtf(sq), 1e-12f);
        float* dst = (path == 0) ? g_ck : g_cq;
        dst[(t0 + t)*KK + l16] = outv;
    }
}

// ---------------------------------------------------------------------------
// Kernel: per-chunk partial state  S[b,c,k,d] = sum_{t in chunk} v[t,d]*ck[t,k]
// ---------------------------------------------------------------------------
__global__ __launch_bounds__(128)
void scan_partial()
{
    int d = blockIdx.x * 128 + threadIdx.x;
    int c = blockIdx.y;
    int b = blockIdx.z;
    __shared__ float cks[LC*KK];

    int base_t = b*LL + c*LC;
    for (int i = threadIdx.x; i < LC*KK; i += 128)
        cks[i] = g_ck[base_t*KK + i];
    __syncthreads();

    float st[KK];
    #pragma unroll
    for (int k = 0; k < KK; ++k) st[k] = 0.f;

    const float* vp = g_value + (size_t)base_t*DD + d;
    for (int t = 0; t < LC; ++t) {
        float v = vp[(size_t)t*DD];
        #pragma unroll
        for (int k = 0; k < KK; ++k) st[k] += v * cks[t*KK + k];
    }
    float* Sp = g_S + ((size_t)(b*NCH + c)*KK)*DD + d;
    #pragma unroll
    for (int k = 0; k < KK; ++k) Sp[(size_t)k*DD] = st[k];
}

// ---------------------------------------------------------------------------
// Kernel: exclusive prefix over chunks — batched loads for MLP
// ---------------------------------------------------------------------------
__global__ __launch_bounds__(256)
void scan_prefix()
{
    int id  = blockIdx.x * 256 + threadIdx.x;   // 0 .. B*K*D-1
    int b   = id >> 14;
    int rem = id & 16383;
    float* base = g_S + (size_t)b*NCH*KK*DD + rem;

    float v[NCH];
    #pragma unroll
    for (int c = 0; c < NCH; ++c)
        v[c] = base[(size_t)c*KK*DD];
    float run = 0.f;
    #pragma unroll
    for (int c = 0; c < NCH; ++c) {
        float t = v[c];
        base[(size_t)c*KK*DD] = run;
        run += t;
    }
}

// ---------------------------------------------------------------------------
// Kernel: apply scan within chunk -> retrieved (scaled 1/sqrt K) into g_ret
// ---------------------------------------------------------------------------
__global__ __launch_bounds__(128)
void scan_apply()
{
    int d = blockIdx.x * 128 + threadIdx.x;
    int c = blockIdx.y;
    int b = blockIdx.z;
    __shared__ float cks[LC*KK];
    __shared__ float cqs[LC*KK];

    int base_t = b*LL + c*LC;
    for (int i = threadIdx.x; i < LC*KK; i += 128) {
        cks[i] = g_ck[base_t*KK + i];
        cqs[i] = g_cq[base_t*KK + i];
    }
    __syncthreads();

    float st[KK];
    const float* Sp = g_S + ((size_t)(b*NCH + c)*KK)*DD + d;
    #pragma unroll
    for (int k = 0; k < KK; ++k) st[k] = Sp[(size_t)k*DD];

    const float* vp = g_value + (size_t)base_t*DD + d;
    float*       rp = g_ret   + (size_t)base_t*DD + d;
    for (int t = 0; t < LC; ++t) {
        float v = vp[(size_t)t*DD];
        float acc = 0.f;
        #pragma unroll
        for (int k = 0; k < KK; ++k) {
            st[k] += v * cks[t*KK + k];
            acc   += cqs[t*KK + k] * st[k];
        }
        rp[(size_t)t*DD] = acc * 0.25f;
    }
}

// ---------------------------------------------------------------------------
// Kernel: LayerNorm on g_ret, fused fp16 panel output (for mma_gemm<1>)
// ---------------------------------------------------------------------------
__global__ __launch_bounds__(256)
void layernorm_conv(const float* __restrict__ gam, const float* __restrict__ bet)
{
    int t = blockIdx.x;
    const float* row = g_ret + (size_t)t*DD;
    __shared__ float sh[DD];
    __shared__ float ws[8], wq[8];
    __shared__ float s_mean, s_rstd;

    int tid  = threadIdx.x;
    int lane = tid & 31;
    int wid  = tid >> 5;

    float4 v = ((const float4*)row)[tid];
    ((float4*)sh)[tid] = v;
    float s = v.x + v.y + v.z + v.w;
    float q = v.x*v.x + v.y*v.y + v.z*v.z + v.w*v.w;
    #pragma unroll
    for (int off = 16; off; off >>= 1) {
        s += __shfl_xor_sync(0xffffffffu, s, off);
        q += __shfl_xor_sync(0xffffffffu, q, off);
    }
    if (lane == 0) { ws[wid] = s; wq[wid] = q; }
    __syncthreads();
    if (tid == 0) {
        float S = 0.f, Q = 0.f;
        #pragma unroll
        for (int i = 0; i < 8; ++i) { S += ws[i]; Q += wq[i]; }
        float m   = S / (float)DD;
        float var = Q / (float)DD - m*m;
        s_mean = m;
        s_rstd = rsqrtf(var + 1e-5f);
    }
    __syncthreads();
    float m = s_mean, r = s_rstd;

    int d0 = tid * 4;
    float nv[4];
    #pragma unroll
    for (int i = 0; i < 4; ++i) {
        int d = d0 + i;
        nv[i] = (sh[d] - m) * r * gam[d] + bet[d];
    }
    int c8    = d0 >> 6;
    int inrow = ((d0 & 63) * 2) ^ ((t & 7) << 4);
    size_t byteoff = ((size_t)c8 * BL + t) * 128 + inrow;
    *(uint2*)((char*)g_ahi + byteoff) = make_uint2(pk2h(nv[0],nv[1]), pk2h(nv[2],nv[3]));
}

// ---------------------------------------------------------------------------
extern "C" void kernel_launch(void* const* d_in, const int* in_sizes, int n_in,
                              void* d_out, int out_size)
{
    const float* x       = (const float*)d_in[0];
    const float* Wv      = (const float*)d_in[1];
    const float* bv      = (const float*)d_in[2];
    const float* Wck     = (const float*)d_in[3];
    const float* bck     = (const float*)d_in[4];
    const float* Wc      = (const float*)d_in[5];
    const float* bc      = (const float*)d_in[6];
    const float* Wcq     = (const float*)d_in[7];
    const float* bcq     = (const float*)d_in[8];
    const float* ln_g    = (const float*)d_in[9];
    const float* ln_b    = (const float*)d_in[10];
    const float* Wo      = (const float*)d_in[11];
    const float* bo      = (const float*)d_in[12];
    const float* pos_key = (const float*)d_in[13];
    float* out = (float*)d_out;

    cudaFuncSetAttribute(mma_gemm<0>, cudaFuncAttributeMaxDynamicSharedMemorySize, GSMEM);
    cudaFuncSetAttribute(mma_gemm<1>, cudaFuncAttributeMaxDynamicSharedMemorySize, GSMEM);

    // weight panels (off critical path)
    conv_w<0><<<(DD*128)/256, 256>>>(Wv);
    conv_w<1><<<(DD*128)/256, 256>>>(Wo);

    // proj + fused x->panel conversion
    proj_kernel<<<BL/PT, 256>>>(x, Wck, bck, Wcq, bcq, Wc, bc, pos_key);

    // value = x @ Wv^T + bv
    mma_gemm<0><<<dim3(DD/256, BL/128), 256, GSMEM>>>(bv, nullptr, nullptr);

    // chunked causal scan
    {
        dim3 grid(DD/128, NCH, BB);
        scan_partial<<<grid, 128>>>();
        scan_prefix<<<(BB*KK*DD)/256, 256>>>();
        scan_apply<<<grid, 128>>>();
    }

    // LayerNorm + fused fp16 conversion into A panel
    layernorm_conv<<<BL, 256>>>(ln_g, ln_b);

    // out = x + normed @ Wo^T + bo
    mma_gemm<1><<<dim3(DD/256, BL/128), 256, GSMEM>>>(bo, x, out);
}

// round 12
// speedup vs baseline: 1.1348x; 1.0242x over previous
#include <cuda_runtime.h>
#include <cuda_bf16.h>
#include <cuda_fp16.h>
#include <math.h>

// Problem constants
#define BB   4
#define LL   2048
#define DD   1024
#define KK   16
#define BL   (BB*LL)        // 8192 tokens
#define NCH  32             // scan chunks
#define LC   (LL/NCH)       // 64 tokens per chunk

// ---------------------------------------------------------------------------
// Scratch (no allocation allowed -> __device__ globals)
// ---------------------------------------------------------------------------
__device__ __half g_valh[BL*DD];            // 16 MB (value, fp16)
__device__ float g_ret  [BL*DD];            // 32 MB (retrieved, pre-LN)
__device__ float g_ck   [BL*KK];
__device__ float g_cq   [BL*KK];
__device__ float g_S    [BB*NCH*KK*DD];     // 8 MB chunk states

// fp16 operand panels, chunk-major, swizzled (cell ^ (row&7)) layout.
__device__ uint4 g_ahi[(16*8192*128)/16];   // 16 MB (x, later normed)
__device__ uint4 g_bhi[(16*1024*128)/16];   // 2 MB  (Wv)
__device__ uint4 g_bhi2[(16*1024*128)/16];  // 2 MB  (Wo)

// ---------------------------------------------------------------------------
// PTX helpers (base sm_90/sm_80 features only — target is plain sm_100!)
// ---------------------------------------------------------------------------
__device__ __forceinline__ unsigned smem_u32(const void* p) {
    unsigned a;
    asm("{ .reg .u64 t; cvta.to.shared.u64 t, %1; cvt.u32.u64 %0, t; }" : "=r"(a) : "l"(p));
    return a;
}

#define MBAR_INIT(addr, cnt) \
    asm volatile("mbarrier.init.shared.b64 [%0], %1;" :: "r"(addr), "r"(cnt) : "memory")
#define MBAR_INVAL(addr) \
    asm volatile("mbarrier.inval.shared.b64 [%0];" :: "r"(addr) : "memory")
#define MBAR_EXPECT_TX(addr, bytes) \
    asm volatile("mbarrier.arrive.expect_tx.shared.b64 _, [%0], %1;" :: "r"(addr), "r"(bytes) : "memory")
#define MBAR_ARRIVE(addr) \
    asm volatile("mbarrier.arrive.shared.b64 _, [%0];" :: "r"(addr) : "memory")

#define MBAR_WAIT(addr, par) do {                                              \
    unsigned _m = (addr), _p = (par), _d;                                      \
    asm volatile("{\n\t.reg .pred p;\n\t"                                      \
        "mbarrier.try_wait.parity.acquire.cta.shared::cta.b64 p, [%1], %2;\n\t"\
        "selp.b32 %0, 1, 0, p;\n\t}"                                           \
        : "=r"(_d) : "r"(_m), "r"(_p) : "memory");                             \
    if (!_d) {                                                                 \
        asm volatile("{\n\t.reg .pred P1;\n\t"                                 \
            "W%=:\n\t"                                                         \
            "mbarrier.try_wait.parity.acquire.cta.shared::cta.b64 P1, [%0], %1, 0x989680;\n\t" \
            "@P1 bra.uni D%=;\n\t"                                             \
            "bra.uni W%=;\n\t"                                                 \
            "D%=:\n\t}" :: "r"(_m), "r"(_p) : "memory");                       \
    }                                                                          \
} while (0)

#define CP_BULK(dst, src, bytes, mbar) \
    asm volatile("cp.async.bulk.shared::cluster.global.mbarrier::complete_tx::bytes [%0], [%1], %2, [%3];" \
        :: "r"(dst), "l"(src), "r"(bytes), "r"(mbar) : "memory")

#define FENCE_PROXY() asm volatile("fence.proxy.async.shared::cta;" ::: "memory")

#define LDSM_X4(r0, r1, r2, r3, addr) \
    asm volatile("ldmatrix.sync.aligned.m8n8.x4.shared.b16 {%0,%1,%2,%3}, [%4];" \
        : "=r"(r0), "=r"(r1), "=r"(r2), "=r"(r3) : "r"(addr))

__device__ __forceinline__ void mma16816h(float* d, const unsigned* a, const unsigned* b) {
    asm volatile("mma.sync.aligned.m16n8k16.row.col.f32.f16.f16.f32 "
        "{%0,%1,%2,%3}, {%4,%5,%6,%7}, {%8,%9}, {%0,%1,%2,%3};"
        : "+f"(d[0]), "+f"(d[1]), "+f"(d[2]), "+f"(d[3])
        : "r"(a[0]), "r"(a[1]), "r"(a[2]), "r"(a[3]), "r"(b[0]), "r"(b[1]));
}

// pack 2 floats -> fp16x2 bits
__device__ __forceinline__ unsigned pk2h(float x, float y) {
    __half2 h = __floats2half2_rn(x, y);
    return *reinterpret_cast<unsigned*>(&h);
}

// ---------------------------------------------------------------------------
// Kernel: conv_w — Wv and Wo (1024x1024 fp32 each) -> fp16 B panels.
// Single launch; blockIdx.x >= half selects Wo.
// ---------------------------------------------------------------------------
#define CONVW_BLOCKS ((DD*128)/256)
__global__ __launch_bounds__(256)
void conv_w(const float* __restrict__ w0, const float* __restrict__ w1)
{
    int bx = blockIdx.x;
    int which = bx >= CONVW_BLOCKS;
    const float* src = which ? w1 : w0;
    uint4* dst = which ? g_bhi2 : g_bhi;
    int id = (bx - which*CONVW_BLOCKS) * 256 + threadIdx.x;  // 0 .. 1024*128-1

    int n = id >> 7;
    int cc = id & 127;
    int c = cc >> 3, cell = cc & 7;
    int k0 = c * 64 + cell * 8;

    const float4* s = (const float4*)(src + (size_t)n * DD + k0);
    float4 a = s[0], b = s[1];

    uint4 H = make_uint4(pk2h(a.x,a.y), pk2h(a.z,a.w), pk2h(b.x,b.y), pk2h(b.z,b.w));
    size_t off16 = ((size_t)c * DD + n) * 8 + (cell ^ (n & 7));
    dst[off16] = H;
}

// ---------------------------------------------------------------------------
// Kernel: mma_gemm — C[8192x1024] = A @ W^T (+bias, optionally +X residual)
// fp16 single-product (fp32 accum). 4-stage cp.async.bulk pipeline, scoped
// mbarrier flow control, register double-buffered ldmatrix.
// CTA tile 128x256, 8 warps (2x4), warp tile 64x64.
// MODE 0: C = g_valh (fp16!), B = Wv panel. MODE 1: C = Cout += X, B = Wo panel.
// ---------------------------------------------------------------------------
#define TILE_A   16384                  // 128x64 fp16
#define TILE_BB  32768                  // 256x64 fp16
#define STG      (TILE_A + TILE_BB)     // 48 KB
#define KBLK     16
#define NSTAGE   4
#define GSMEM    (1024 + NSTAGE*STG)    // 197632
#define NWARP    8

template<int MODE>
__global__ __launch_bounds__(256, 1)
void mma_gemm(const float* __restrict__ bias, const float* __restrict__ X,
              float* __restrict__ Cout)
{
    extern __shared__ char smem[];
    unsigned sb = smem_u32(smem);
    int tid = threadIdx.x, lane = tid & 31, wid = tid >> 5;
    int wm = wid & 1, wn = wid >> 1;          // 2 x 4 warp grid, 64x64 tiles
    int bn = blockIdx.x * 256, bm = blockIdx.y * 128;

    // mbarriers: full[s] at sb+8+16s, cons[s] at sb+16+16s
    if (tid == 0) {
        #pragma unroll
        for (int s = 0; s < NSTAGE; ++s) {
            MBAR_INIT(sb + 8  + 16*s, 1);
            MBAR_INIT(sb + 16 + 16*s, NWARP);
        }
        FENCE_PROXY();
    }
    __syncthreads();

    const char* pA = (const char*)g_ahi;
    const char* pB = (MODE == 0) ? (const char*)g_bhi : (const char*)g_bhi2;

    auto issue = [&](int kb, int s) {
        unsigned st = sb + 1024 + s * STG;
        unsigned fm = sb + 8 + 16*s;
        size_t aoff = ((size_t)kb * BL + bm) * 128;
        size_t boff = ((size_t)kb * DD + bn) * 128;
        MBAR_EXPECT_TX(fm, STG);
        CP_BULK(st,          pA + aoff, TILE_A,  fm);
        CP_BULK(st + TILE_A, pB + boff, TILE_BB, fm);
    };
    if (tid == 0) {
        #pragma unroll
        for (int s = 0; s < NSTAGE - 1; ++s) issue(s, s);
    }

    float acc[4][8][4];
    #pragma unroll
    for (int i = 0; i < 4; ++i)
        #pragma unroll
        for (int j = 0; j < 8; ++j)
            #pragma unroll
            for (int q = 0; q < 4; ++q) acc[i][j][q] = 0.f;

    int rl = (lane & 7) + ((lane >> 3) & 1) * 8;
    int cs = lane >> 4;

    int rA[4], sA[4], rB[4], sB[4];
    #pragma unroll
    for (int i = 0; i < 4; ++i) { int r = wm*64 + i*16 + rl; rA[i] = r*128; sA[i] = r & 7; }
    #pragma unroll
    for (int j = 0; j < 4; ++j) { int r = wn*64 + j*16 + rl; rB[j] = r*128; sB[j] = r & 7; }

    // operand double buffers: A 16 regs, B 16 regs per buffer
    unsigned opA[2][16], opB[2][16];

    auto load_ops = [&](unsigned bA, unsigned bBp, int ks, unsigned* A, unsigned* B) {
        int cc = ks * 2 + cs;
        #pragma unroll
        for (int i = 0; i < 4; ++i) {
            unsigned off = rA[i] + ((cc ^ sA[i]) << 4);
            LDSM_X4(A[i*4+0], A[i*4+1], A[i*4+2], A[i*4+3], bA + off);
        }
        #pragma unroll
        for (int j = 0; j < 4; ++j) {
            unsigned off = rB[j] + ((cc ^ sB[j]) << 4);
            unsigned r0, r1, r2, r3;
            LDSM_X4(r0, r1, r2, r3, bBp + off);
            B[j*4+0] = r0; B[j*4+1] = r2; B[j*4+2] = r1; B[j*4+3] = r3;
        }
    };

    auto do_mma = [&](const unsigned* A, const unsigned* B) {
        #pragma unroll
        for (int jt = 0; jt < 4; ++jt)
            #pragma unroll
            for (int h = 0; h < 2; ++h) {
                const unsigned* Bf = B + jt*4 + h*2;
                #pragma unroll
                for (int i = 0; i < 4; ++i)
                    mma16816h(acc[i][jt*2+h], A + i*4, Bf);
            }
    };

    for (int kb = 0; kb < KBLK; ++kb) {
        int s  = kb % NSTAGE;
        int ph = (kb / NSTAGE) & 1;
        MBAR_WAIT(sb + 8 + 16*s, ph);
        unsigned st = sb + 1024 + s * STG;
        unsigned bA = st, bBp = st + TILE_A;

        load_ops(bA, bBp, 0, opA[0], opB[0]);
        #pragma unroll
        for (int ks = 0; ks < 4; ++ks) {
            int cur = ks & 1;
            if (ks < 3) load_ops(bA, bBp, ks + 1, opA[cur^1], opB[cur^1]);
            do_mma(opA[cur], opB[cur]);
        }

        if (lane == 0) MBAR_ARRIVE(sb + 16 + 16*s);
        if (tid == 0 && kb + NSTAGE - 1 < KBLK) {
            MBAR_WAIT(sb + 16 + 16*s, ph);
            issue(kb + NSTAGE - 1, (kb + NSTAGE - 1) % NSTAGE);
        }
    }

    // epilogue: warp writes its 64x64 sub-tile
    #pragma unroll
    for (int i = 0; i < 4; ++i) {
        int r0 = bm + wm*64 + i*16 + (lane >> 2);
        #pragma unroll
        for (int j = 0; j < 8; ++j) {
            int col = bn + wn*64 + j*8 + (lane & 3)*2;
            float2 b2 = *(const float2*)(bias + col);
            float2 v0 = make_float2(acc[i][j][0] + b2.x, acc[i][j][1] + b2.y);
            float2 v1 = make_float2(acc[i][j][2] + b2.x, acc[i][j][3] + b2.y);
            if (MODE == 1) {
                float2 x0 = *(const float2*)(X + (size_t)r0*DD + col);
                float2 x1 = *(const float2*)(X + (size_t)(r0+8)*DD + col);
                v0.x += x0.x; v0.y += x0.y;
                v1.x += x1.x; v1.y += x1.y;
                *(float2*)(Cout + (size_t)r0*DD + col)     = v0;
                *(float2*)(Cout + (size_t)(r0+8)*DD + col) = v1;
            } else {
                *(__half2*)(&g_valh[(size_t)r0*DD + col])     = __floats2half2_rn(v0.x, v0.y);
                *(__half2*)(&g_valh[(size_t)(r0+8)*DD + col]) = __floats2half2_rn(v1.x, v1.y);
            }
        }
    }

    __syncthreads();
    if (tid == 0) {
        #pragma unroll
        for (int s = 0; s < NSTAGE; ++s) {
            MBAR_INVAL(sb + 8  + 16*s);
            MBAR_INVAL(sb + 16 + 16*s);
        }
    }
}

// ---------------------------------------------------------------------------
// Kernel: proj — content key/query + combiner for 8 tokens per block,
// FUSED with x -> fp16 A-panel conversion (reads x once).
// ---------------------------------------------------------------------------
#define PT 8
__global__ __launch_bounds__(256)
void proj_kernel(const float* __restrict__ x,
                 const float* __restrict__ Wck, const float* __restrict__ bck,
                 const float* __restrict__ Wcq, const float* __restrict__ bcq,
                 const float* __restrict__ Wc,  const float* __restrict__ bc,
                 const float* __restrict__ pos_key)
{
    int t0   = blockIdx.x * PT;
    int tid  = threadIdx.x;
    int lane = tid & 31;
    int warp = tid >> 5;

    __shared__ float xs[PT][DD];
    __shared__ float dots[2][PT][16];
    __shared__ float pos_s[PT][16];

    #pragma unroll
    for (int i = tid; i < PT*DD/4; i += 256)
        ((float4*)&xs[0][0])[i] = ((const float4*)(x + (size_t)t0*DD))[i];
    if (tid < PT*16) {
        int tt = tid >> 4, k = tid & 15;
        int l = (t0 + tt) & (LL-1);
        pos_s[tt][k] = pos_key[l*KK + k];
    }
    __syncthreads();

    // --- fused conv: emit fp16 panel rows ---
    {
        int tt   = tid >> 5;
        int t    = t0 + tt;
        int cell = lane & 7;
        #pragma unroll
        for (int q = 0; q < 4; ++q) {
            int c  = (lane >> 3) + q*4;
            int k0 = c*64 + cell*8;
            const float* v = &xs[tt][k0];
            uint4 H = make_uint4(pk2h(v[0],v[1]), pk2h(v[2],v[3]),
                                 pk2h(v[4],v[5]), pk2h(v[6],v[7]));
            size_t off16 = ((size_t)c * BL + t) * 8 + (cell ^ (t & 7));
            g_ahi[off16] = H;
        }
    }

    // --- 32 dot products; each warp does 4 (sequential — keeps regs low) ---
    #pragma unroll 1
    for (int oo = 0; oo < 4; ++oo) {
        int o = warp + oo*8;
        const float* W = (o < 16) ? (Wck + (size_t)o*DD) : (Wcq + (size_t)(o-16)*DD);
        float bias_o   = (o < 16) ? bck[o] : bcq[o-16];
        float wreg[32];
        #pragma unroll
        for (int i = 0; i < 32; ++i) wreg[i] = W[lane + 32*i];
        #pragma unroll
        for (int t = 0; t < PT; ++t) {
            float s = 0.f;
            #pragma unroll
            for (int i = 0; i < 32; ++i) s += wreg[i] * xs[t][lane + 32*i];
            #pragma unroll
            for (int off = 16; off; off >>= 1)
                s += __shfl_xor_sync(0xffffffffu, s, off);
            if (lane == 0)
                dots[o >> 4][t][o & 15] = s + bias_o;
        }
    }
    __syncthreads();

    // --- normalize + combiner + normalize ---
    {
        int t    = warp;
        int path = lane >> 4;
        int l16  = lane & 15;

        float v = dots[path][t][l16];
        float ss = v*v;
        #pragma unroll
        for (int off = 8; off; off >>= 1)
            ss += __shfl_xor_sync(0xffffffffu, ss, off, 16);
        float cnv = v / fmaxf(sqrtf(ss), 1e-12f);

        float s = bc[l16];
        #pragma unroll
        for (int j = 0; j < 16; ++j) {
            float cj = __shfl_sync(0xffffffffu, cnv, j, 16);
            s += Wc[l16*32 + j]      * pos_s[t][j];
            s += Wc[l16*32 + 16 + j] * cj;
        }
        s = tanhf(s);
        float sq = s*s;
        #pragma unroll
        for (int off = 8; off; off >>= 1)
            sq += __shfl_xor_sync(0xffffffffu, sq, off, 16);
        float outv = s / fmaxf(sqrtf(sq), 1e-12f);
        float* dst = (path == 0) ? g_ck : g_cq;
        dst[(t0 + t)*KK + l16] = outv;
    }
}

// ---------------------------------------------------------------------------
// Kernel: per-chunk partial state  S[b,c,k,d] = sum_{t in chunk} v[t,d]*ck[t,k]
// (value read as fp16)
// ---------------------------------------------------------------------------
__global__ __launch_bounds__(128)
void scan_partial()
{
    int d = blockIdx.x * 128 + threadIdx.x;
    int c = blockIdx.y;
    int b = blockIdx.z;
    __shared__ float cks[LC*KK];

    int base_t = b*LL + c*LC;
    for (int i = threadIdx.x; i < LC*KK; i += 128)
        cks[i] = g_ck[base_t*KK + i];
    __syncthreads();

    float st[KK];
    #pragma unroll
    for (int k = 0; k < KK; ++k) st[k] = 0.f;

    const __half* vp = g_valh + (size_t)base_t*DD + d;
    for (int t = 0; t < LC; ++t) {
        float v = __half2float(vp[(size_t)t*DD]);
        #pragma unroll
        for (int k = 0; k < KK; ++k) st[k] += v * cks[t*KK + k];
    }
    float* Sp = g_S + ((size_t)(b*NCH + c)*KK)*DD + d;
    #pragma unroll
    for (int k = 0; k < KK; ++k) Sp[(size_t)k*DD] = st[k];
}

// ---------------------------------------------------------------------------
// Kernel: exclusive prefix over chunks — batched loads for MLP
// ---------------------------------------------------------------------------
__global__ __launch_bounds__(256)
void scan_prefix()
{
    int id  = blockIdx.x * 256 + threadIdx.x;   // 0 .. B*K*D-1
    int b   = id >> 14;
    int rem = id & 16383;
    float* base = g_S + (size_t)b*NCH*KK*DD + rem;

    float v[NCH];
    #pragma unroll
    for (int c = 0; c < NCH; ++c)
        v[c] = base[(size_t)c*KK*DD];
    float run = 0.f;
    #pragma unroll
    for (int c = 0; c < NCH; ++c) {
        float t = v[c];
        base[(size_t)c*KK*DD] = run;
        run += t;
    }
}

// ---------------------------------------------------------------------------
// Kernel: apply scan within chunk -> retrieved (scaled 1/sqrt K) into g_ret
// (value read as fp16)
// ---------------------------------------------------------------------------
__global__ __launch_bounds__(128)
void scan_apply()
{
    int d = blockIdx.x * 128 + threadIdx.x;
    int c = blockIdx.y;
    int b = blockIdx.z;
    __shared__ float cks[LC*KK];
    __shared__ float cqs[LC*KK];

    int base_t = b*LL + c*LC;
    for (int i = threadIdx.x; i < LC*KK; i += 128) {
        cks[i] = g_ck[base_t*KK + i];
        cqs[i] = g_cq[base_t*KK + i];
    }
    __syncthreads();

    float st[KK];
    const float* Sp = g_S + ((size_t)(b*NCH + c)*KK)*DD + d;
    #pragma unroll
    for (int k = 0; k < KK; ++k) st[k] = Sp[(size_t)k*DD];

    const __half* vp = g_valh + (size_t)base_t*DD + d;
    float*        rp = g_ret  + (size_t)base_t*DD + d;
    for (int t = 0; t < LC; ++t) {
        float v = __half2float(vp[(size_t)t*DD]);
        float acc = 0.f;
        #pragma unroll
        for (int k = 0; k < KK; ++k) {
            st[k] += v * cks[t*KK + k];
            acc   += cqs[t*KK + k] * st[k];
        }
        rp[(size_t)t*DD] = acc * 0.25f;
    }
}

// ---------------------------------------------------------------------------
// Kernel: LayerNorm on g_ret, fused fp16 panel output (for mma_gemm<1>)
// ---------------------------------------------------------------------------
__global__ __launch_bounds__(256)
void layernorm_conv(const float* __restrict__ gam, const float* __restrict__ bet)
{
    int t = blockIdx.x;
    const float* row = g_ret + (size_t)t*DD;
    __shared__ float sh[DD];
    __shared__ float ws[8], wq[8];
    __shared__ float s_mean, s_rstd;

    int tid  = threadIdx.x;
    int lane = tid & 31;
    int wid  = tid >> 5;

    float4 v = ((const float4*)row)[tid];
    ((float4*)sh)[tid] = v;
    float s = v.x + v.y + v.z + v.w;
    float q = v.x*v.x + v.y*v.y + v.z*v.z + v.w*v.w;
    #pragma unroll
    for (int off = 16; off; off >>= 1) {
        s += __shfl_xor_sync(0xffffffffu, s, off);
        q += __shfl_xor_sync(0xffffffffu, q, off);
    }
    if (lane == 0) { ws[wid] = s; wq[wid] = q; }
    __syncthreads();
    if (tid == 0) {
        float S = 0.f, Q = 0.f;
        #pragma unroll
        for (int i = 0; i < 8; ++i) { S += ws[i]; Q += wq[i]; }
        float m   = S / (float)DD;
        float var = Q / (float)DD - m*m;
        s_mean = m;
        s_rstd = rsqrtf(var + 1e-5f);
    }
    __syncthreads();
    float m = s_mean, r = s_rstd;

    int d0 = tid * 4;
    float nv[4];
    #pragma unroll
    for (int i = 0; i < 4; ++i) {
        int d = d0 + i;
        nv[i] = (sh[d] - m) * r * gam[d] + bet[d];
    }
    int c8    = d0 >> 6;
    int inrow = ((d0 & 63) * 2) ^ ((t & 7) << 4);
    size_t byteoff = ((size_t)c8 * BL + t) * 128 + inrow;
    *(uint2*)((char*)g_ahi + byteoff) = make_uint2(pk2h(nv[0],nv[1]), pk2h(nv[2],nv[3]));
}

// ---------------------------------------------------------------------------
extern "C" void kernel_launch(void* const* d_in, const int* in_sizes, int n_in,
                              void* d_out, int out_size)
{
    const float* x       = (const float*)d_in[0];
    const float* Wv      = (const float*)d_in[1];
    const float* bv      = (const float*)d_in[2];
    const float* Wck     = (const float*)d_in[3];
    const float* bck     = (const float*)d_in[4];
    const float* Wc      = (const float*)d_in[5];
    const float* bc      = (const float*)d_in[6];
    const float* Wcq     = (const float*)d_in[7];
    const float* bcq     = (const float*)d_in[8];
    const float* ln_g    = (const float*)d_in[9];
    const float* ln_b    = (const float*)d_in[10];
    const float* Wo      = (const float*)d_in[11];
    const float* bo      = (const float*)d_in[12];
    const float* pos_key = (const float*)d_in[13];
    float* out = (float*)d_out;

    cudaFuncSetAttribute(mma_gemm<0>, cudaFuncAttributeMaxDynamicSharedMemorySize, GSMEM);
    cudaFuncSetAttribute(mma_gemm<1>, cudaFuncAttributeMaxDynamicSharedMemorySize, GSMEM);

    // both weight panels in one launch (off critical path)
    conv_w<<<2*CONVW_BLOCKS, 256>>>(Wv, Wo);

    // proj + fused x->panel conversion
    proj_kernel<<<BL/PT, 256>>>(x, Wck, bck, Wcq, bcq, Wc, bc, pos_key);

    // value = x @ Wv^T + bv  (written as fp16 into g_valh)
    mma_gemm<0><<<dim3(DD/256, BL/128), 256, GSMEM>>>(bv, nullptr, nullptr);

    // chunked causal scan
    {
        dim3 grid(DD/128, NCH, BB);
        scan_partial<<<grid, 128>>>();
        scan_prefix<<<(BB*KK*DD)/256, 256>>>();
        scan_apply<<<grid, 128>>>();
    }

    // LayerNorm + fused fp16 conversion into A panel
    layernorm_conv<<<BL, 256>>>(ln_g, ln_b);

    // out = x + normed @ Wo^T + bo
    mma_gemm<1><<<dim3(DD/256, BL/128), 256, GSMEM>>>(bo, x, out);
}

// round 13
// speedup vs baseline: 1.1439x; 1.0080x over previous
#include <cuda_runtime.h>
#include <cuda_bf16.h>
#include <cuda_fp16.h>
#include <math.h>

// Problem constants
#define BB   4
#define LL   2048
#define DD   1024
#define KK   16
#define BL   (BB*LL)        // 8192 tokens
#define NCH  32             // scan chunks
#define LC   (LL/NCH)       // 64 tokens per chunk

// ---------------------------------------------------------------------------
// Scratch (no allocation allowed -> __device__ globals)
// ---------------------------------------------------------------------------
__device__ __half g_valh[BL*DD];            // 16 MB (value, fp16)
__device__ __half g_reth[BL*DD];            // 16 MB (retrieved, fp16, pre-LN)
__device__ float g_ck   [BL*KK];
__device__ float g_cq   [BL*KK];
__device__ float g_S    [BB*NCH*KK*DD];     // 8 MB chunk states

// fp16 operand panels, chunk-major, swizzled (cell ^ (row&7)) layout.
__device__ uint4 g_ahi[(16*8192*128)/16];   // 16 MB (x, later normed)
__device__ uint4 g_bhi[(16*1024*128)/16];   // 2 MB  (Wv)
__device__ uint4 g_bhi2[(16*1024*128)/16];  // 2 MB  (Wo)

// ---------------------------------------------------------------------------
// PTX helpers (base sm_90/sm_80 features only — target is plain sm_100!)
// ---------------------------------------------------------------------------
__device__ __forceinline__ unsigned smem_u32(const void* p) {
    unsigned a;
    asm("{ .reg .u64 t; cvta.to.shared.u64 t, %1; cvt.u32.u64 %0, t; }" : "=r"(a) : "l"(p));
    return a;
}

#define MBAR_INIT(addr, cnt) \
    asm volatile("mbarrier.init.shared.b64 [%0], %1;" :: "r"(addr), "r"(cnt) : "memory")
#define MBAR_INVAL(addr) \
    asm volatile("mbarrier.inval.shared.b64 [%0];" :: "r"(addr) : "memory")
#define MBAR_EXPECT_TX(addr, bytes) \
    asm volatile("mbarrier.arrive.expect_tx.shared.b64 _, [%0], %1;" :: "r"(addr), "r"(bytes) : "memory")
#define MBAR_ARRIVE(addr) \
    asm volatile("mbarrier.arrive.shared.b64 _, [%0];" :: "r"(addr) : "memory")

#define MBAR_WAIT(addr, par) do {                                              \
    unsigned _m = (addr), _p = (par), _d;                                      \
    asm volatile("{\n\t.reg .pred p;\n\t"                                      \
        "mbarrier.try_wait.parity.acquire.cta.shared::cta.b64 p, [%1], %2;\n\t"\
        "selp.b32 %0, 1, 0, p;\n\t}"                                           \
        : "=r"(_d) : "r"(_m), "r"(_p) : "memory");                             \
    if (!_d) {                                                                 \
        asm volatile("{\n\t.reg .pred P1;\n\t"                                 \
            "W%=:\n\t"                                                         \
            "mbarrier.try_wait.parity.acquire.cta.shared::cta.b64 P1, [%0], %1, 0x989680;\n\t" \
            "@P1 bra.uni D%=;\n\t"                                             \
            "bra.uni W%=;\n\t"                                                 \
            "D%=:\n\t}" :: "r"(_m), "r"(_p) : "memory");                       \
    }                                                                          \
} while (0)

#define CP_BULK(dst, src, bytes, mbar) \
    asm volatile("cp.async.bulk.shared::cluster.global.mbarrier::complete_tx::bytes [%0], [%1], %2, [%3];" \
        :: "r"(dst), "l"(src), "r"(bytes), "r"(mbar) : "memory")

#define FENCE_PROXY() asm volatile("fence.proxy.async.shared::cta;" ::: "memory")

#define LDSM_X4(r0, r1, r2, r3, addr) \
    asm volatile("ldmatrix.sync.aligned.m8n8.x4.shared.b16 {%0,%1,%2,%3}, [%4];" \
        : "=r"(r0), "=r"(r1), "=r"(r2), "=r"(r3) : "r"(addr))

__device__ __forceinline__ void mma16816h(float* d, const unsigned* a, const unsigned* b) {
    asm volatile("mma.sync.aligned.m16n8k16.row.col.f32.f16.f16.f32 "
        "{%0,%1,%2,%3}, {%4,%5,%6,%7}, {%8,%9}, {%0,%1,%2,%3};"
        : "+f"(d[0]), "+f"(d[1]), "+f"(d[2]), "+f"(d[3])
        : "r"(a[0]), "r"(a[1]), "r"(a[2]), "r"(a[3]), "r"(b[0]), "r"(b[1]));
}

// pack 2 floats -> fp16x2 bits
__device__ __forceinline__ unsigned pk2h(float x, float y) {
    __half2 h = __floats2half2_rn(x, y);
    return *reinterpret_cast<unsigned*>(&h);
}

// ---------------------------------------------------------------------------
// Kernel: conv_w — Wv and Wo (1024x1024 fp32 each) -> fp16 B panels.
// Single launch; blockIdx.x >= half selects Wo.
// ---------------------------------------------------------------------------
#define CONVW_BLOCKS ((DD*128)/256)
__global__ __launch_bounds__(256)
void conv_w(const float* __restrict__ w0, const float* __restrict__ w1)
{
    int bx = blockIdx.x;
    int which = bx >= CONVW_BLOCKS;
    const float* src = which ? w1 : w0;
    uint4* dst = which ? g_bhi2 : g_bhi;
    int id = (bx - which*CONVW_BLOCKS) * 256 + threadIdx.x;  // 0 .. 1024*128-1

    int n = id >> 7;
    int cc = id & 127;
    int c = cc >> 3, cell = cc & 7;
    int k0 = c * 64 + cell * 8;

    const float4* s = (const float4*)(src + (size_t)n * DD + k0);
    float4 a = s[0], b = s[1];

    uint4 H = make_uint4(pk2h(a.x,a.y), pk2h(a.z,a.w), pk2h(b.x,b.y), pk2h(b.z,b.w));
    size_t off16 = ((size_t)c * DD + n) * 8 + (cell ^ (n & 7));
    dst[off16] = H;
}

// ---------------------------------------------------------------------------
// Kernel: mma_gemm — C[8192x1024] = A @ W^T (+bias, optionally +X residual)
// fp16 single-product (fp32 accum). 4-stage cp.async.bulk pipeline, scoped
// mbarrier flow control, register double-buffered ldmatrix.
// CTA tile 128x256, 8 warps (2x4), warp tile 64x64.
// MODE 0: C = g_valh (fp16), B = Wv panel. MODE 1: C = Cout += X, B = Wo panel.
// ---------------------------------------------------------------------------
#define TILE_A   16384                  // 128x64 fp16
#define TILE_BB  32768                  // 256x64 fp16
#define STG      (TILE_A + TILE_BB)     // 48 KB
#define KBLK     16
#define NSTAGE   4
#define GSMEM    (1024 + NSTAGE*STG)    // 197632
#define NWARP    8

template<int MODE>
__global__ __launch_bounds__(256, 1)
void mma_gemm(const float* __restrict__ bias, const float* __restrict__ X,
              float* __restrict__ Cout)
{
    extern __shared__ char smem[];
    unsigned sb = smem_u32(smem);
    int tid = threadIdx.x, lane = tid & 31, wid = tid >> 5;
    int wm = wid & 1, wn = wid >> 1;          // 2 x 4 warp grid, 64x64 tiles
    int bn = blockIdx.x * 256, bm = blockIdx.y * 128;

    if (tid == 0) {
        #pragma unroll
        for (int s = 0; s < NSTAGE; ++s) {
            MBAR_INIT(sb + 8  + 16*s, 1);
            MBAR_INIT(sb + 16 + 16*s, NWARP);
        }
        FENCE_PROXY();
    }
    __syncthreads();

    const char* pA = (const char*)g_ahi;
    const char* pB = (MODE == 0) ? (const char*)g_bhi : (const char*)g_bhi2;

    auto issue = [&](int kb, int s) {
        unsigned st = sb + 1024 + s * STG;
        unsigned fm = sb + 8 + 16*s;
        size_t aoff = ((size_t)kb * BL + bm) * 128;
        size_t boff = ((size_t)kb * DD + bn) * 128;
        MBAR_EXPECT_TX(fm, STG);
        CP_BULK(st,          pA + aoff, TILE_A,  fm);
        CP_BULK(st + TILE_A, pB + boff, TILE_BB, fm);
    };
    if (tid == 0) {
        #pragma unroll
        for (int s = 0; s < NSTAGE - 1; ++s) issue(s, s);
    }

    float acc[4][8][4];
    #pragma unroll
    for (int i = 0; i < 4; ++i)
        #pragma unroll
        for (int j = 0; j < 8; ++j)
            #pragma unroll
            for (int q = 0; q < 4; ++q) acc[i][j][q] = 0.f;

    int rl = (lane & 7) + ((lane >> 3) & 1) * 8;
    int cs = lane >> 4;

    int rA[4], sA[4], rB[4], sB[4];
    #pragma unroll
    for (int i = 0; i < 4; ++i) { int r = wm*64 + i*16 + rl; rA[i] = r*128; sA[i] = r & 7; }
    #pragma unroll
    for (int j = 0; j < 4; ++j) { int r = wn*64 + j*16 + rl; rB[j] = r*128; sB[j] = r & 7; }

    unsigned opA[2][16], opB[2][16];

    auto load_ops = [&](unsigned bA, unsigned bBp, int ks, unsigned* A, unsigned* B) {
        int cc = ks * 2 + cs;
        #pragma unroll
        for (int i = 0; i < 4; ++i) {
            unsigned off = rA[i] + ((cc ^ sA[i]) << 4);
            LDSM_X4(A[i*4+0], A[i*4+1], A[i*4+2], A[i*4+3], bA + off);
        }
        #pragma unroll
        for (int j = 0; j < 4; ++j) {
            unsigned off = rB[j] + ((cc ^ sB[j]) << 4);
            unsigned r0, r1, r2, r3;
            LDSM_X4(r0, r1, r2, r3, bBp + off);
            B[j*4+0] = r0; B[j*4+1] = r2; B[j*4+2] = r1; B[j*4+3] = r3;
        }
    };

    auto do_mma = [&](const unsigned* A, const unsigned* B) {
        #pragma unroll
        for (int jt = 0; jt < 4; ++jt)
            #pragma unroll
            for (int h = 0; h < 2; ++h) {
                const unsigned* Bf = B + jt*4 + h*2;
                #pragma unroll
                for (int i = 0; i < 4; ++i)
                    mma16816h(acc[i][jt*2+h], A + i*4, Bf);
            }
    };

    for (int kb = 0; kb < KBLK; ++kb) {
        int s  = kb % NSTAGE;
        int ph = (kb / NSTAGE) & 1;
        MBAR_WAIT(sb + 8 + 16*s, ph);
        unsigned st = sb + 1024 + s * STG;
        unsigned bA = st, bBp = st + TILE_A;

        load_ops(bA, bBp, 0, opA[0], opB[0]);
        #pragma unroll
        for (int ks = 0; ks < 4; ++ks) {
            int cur = ks & 1;
            if (ks < 3) load_ops(bA, bBp, ks + 1, opA[cur^1], opB[cur^1]);
            do_mma(opA[cur], opB[cur]);
        }

        if (lane == 0) MBAR_ARRIVE(sb + 16 + 16*s);
        if (tid == 0 && kb + NSTAGE - 1 < KBLK) {
            MBAR_WAIT(sb + 16 + 16*s, ph);
            issue(kb + NSTAGE - 1, (kb + NSTAGE - 1) % NSTAGE);
        }
    }

    // epilogue: warp writes its 64x64 sub-tile
    #pragma unroll
    for (int i = 0; i < 4; ++i) {
        int r0 = bm + wm*64 + i*16 + (lane >> 2);
        #pragma unroll
        for (int j = 0; j < 8; ++j) {
            int col = bn + wn*64 + j*8 + (lane & 3)*2;
            float2 b2 = *(const float2*)(bias + col);
            float2 v0 = make_float2(acc[i][j][0] + b2.x, acc[i][j][1] + b2.y);
            float2 v1 = make_float2(acc[i][j][2] + b2.x, acc[i][j][3] + b2.y);
            if (MODE == 1) {
                float2 x0 = *(const float2*)(X + (size_t)r0*DD + col);
                float2 x1 = *(const float2*)(X + (size_t)(r0+8)*DD + col);
                v0.x += x0.x; v0.y += x0.y;
                v1.x += x1.x; v1.y += x1.y;
                *(float2*)(Cout + (size_t)r0*DD + col)     = v0;
                *(float2*)(Cout + (size_t)(r0+8)*DD + col) = v1;
            } else {
                *(__half2*)(&g_valh[(size_t)r0*DD + col])     = __floats2half2_rn(v0.x, v0.y);
                *(__half2*)(&g_valh[(size_t)(r0+8)*DD + col]) = __floats2half2_rn(v1.x, v1.y);
            }
        }
    }

    __syncthreads();
    if (tid == 0) {
        #pragma unroll
        for (int s = 0; s < NSTAGE; ++s) {
            MBAR_INVAL(sb + 8  + 16*s);
            MBAR_INVAL(sb + 16 + 16*s);
        }
    }
}

// ---------------------------------------------------------------------------
// Kernel: proj — content key/query + combiner for 8 tokens per block,
// FUSED with x -> fp16 A-panel conversion (reads x once).
// ---------------------------------------------------------------------------
#define PT 8
__global__ __launch_bounds__(256)
void proj_kernel(const float* __restrict__ x,
                 const float* __restrict__ Wck, const float* __restrict__ bck,
                 const float* __restrict__ Wcq, const float* __restrict__ bcq,
                 const float* __restrict__ Wc,  const float* __restrict__ bc,
                 const float* __restrict__ pos_key)
{
    int t0   = blockIdx.x * PT;
    int tid  = threadIdx.x;
    int lane = tid & 31;
    int warp = tid >> 5;

    __shared__ float xs[PT][DD];
    __shared__ float dots[2][PT][16];
    __shared__ float pos_s[PT][16];

    #pragma unroll
    for (int i = tid; i < PT*DD/4; i += 256)
        ((float4*)&xs[0][0])[i] = ((const float4*)(x + (size_t)t0*DD))[i];
    if (tid < PT*16) {
        int tt = tid >> 4, k = tid & 15;
        int l = (t0 + tt) & (LL-1);
        pos_s[tt][k] = pos_key[l*KK + k];
    }
    __syncthreads();

    // --- fused conv: emit fp16 panel rows ---
    {
        int tt   = tid >> 5;
        int t    = t0 + tt;
        int cell = lane & 7;
        #pragma unroll
        for (int q = 0; q < 4; ++q) {
            int c  = (lane >> 3) + q*4;
            int k0 = c*64 + cell*8;
            const float* v = &xs[tt][k0];
            uint4 H = make_uint4(pk2h(v[0],v[1]), pk2h(v[2],v[3]),
                                 pk2h(v[4],v[5]), pk2h(v[6],v[7]));
            size_t off16 = ((size_t)c * BL + t) * 8 + (cell ^ (t & 7));
            g_ahi[off16] = H;
        }
    }

    // --- 32 dot products; each warp does 4 (sequential — keeps regs low) ---
    #pragma unroll 1
    for (int oo = 0; oo < 4; ++oo) {
        int o = warp + oo*8;
        const float* W = (o < 16) ? (Wck + (size_t)o*DD) : (Wcq + (size_t)(o-16)*DD);
        float bias_o   = (o < 16) ? bck[o] : bcq[o-16];
        float wreg[32];
        #pragma unroll
        for (int i = 0; i < 32; ++i) wreg[i] = W[lane + 32*i];
        #pragma unroll
        for (int t = 0; t < PT; ++t) {
            float s = 0.f;
            #pragma unroll
            for (int i = 0; i < 32; ++i) s += wreg[i] * xs[t][lane + 32*i];
            #pragma unroll
            for (int off = 16; off; off >>= 1)
                s += __shfl_xor_sync(0xffffffffu, s, off);
            if (lane == 0)
                dots[o >> 4][t][o & 15] = s + bias_o;
        }
    }
    __syncthreads();

    // --- normalize + combiner + normalize ---
    {
        int t    = warp;
        int path = lane >> 4;
        int l16  = lane & 15;

        float v = dots[path][t][l16];
        float ss = v*v;
        #pragma unroll
        for (int off = 8; off; off >>= 1)
            ss += __shfl_xor_sync(0xffffffffu, ss, off, 16);
        float cnv = v / fmaxf(sqrtf(ss), 1e-12f);

        float s = bc[l16];
        #pragma unroll
        for (int j = 0; j < 16; ++j) {
            float cj = __shfl_sync(0xffffffffu, cnv, j, 16);
            s += Wc[l16*32 + j]      * pos_s[t][j];
            s += Wc[l16*32 + 16 + j] * cj;
        }
        s = tanhf(s);
        float sq = s*s;
        #pragma unroll
        for (int off = 8; off; off >>= 1)
            sq += __shfl_xor_sync(0xffffffffu, sq, off, 16);
        float outv = s / fmaxf(sqrtf(sq), 1e-12f);
        float* dst = (path == 0) ? g_ck : g_cq;
        dst[(t0 + t)*KK + l16] = outv;
    }
}

// ---------------------------------------------------------------------------
// Kernel: per-chunk partial state, 2 d-columns per thread (half2 loads).
// grid = (DD/256, NCH, BB), 128 threads.
// ---------------------------------------------------------------------------
__global__ __launch_bounds__(128)
void scan_partial()
{
    int d2 = blockIdx.x * 128 + threadIdx.x;   // 0..511 -> pair (2*d2, 2*d2+1)
    int c = blockIdx.y;
    int b = blockIdx.z;
    __shared__ float cks[LC*KK];

    int base_t = b*LL + c*LC;
    for (int i = threadIdx.x; i < LC*KK; i += 128)
        cks[i] = g_ck[base_t*KK + i];
    __syncthreads();

    float sx[KK], sy[KK];
    #pragma unroll
    for (int k = 0; k < KK; ++k) { sx[k] = 0.f; sy[k] = 0.f; }

    const __half2* vp = (const __half2*)(g_valh + (size_t)base_t*DD) + d2;
    for (int t = 0; t < LC; ++t) {
        float2 v = __half22float2(vp[(size_t)t*(DD/2)]);
        #pragma unroll
        for (int k = 0; k < KK; ++k) {
            float ckv = cks[t*KK + k];
            sx[k] += v.x * ckv;
            sy[k] += v.y * ckv;
        }
    }
    float2* Sp = (float2*)(g_S + ((size_t)(b*NCH + c)*KK)*DD) + d2;
    #pragma unroll
    for (int k = 0; k < KK; ++k)
        Sp[(size_t)k*(DD/2)] = make_float2(sx[k], sy[k]);
}

// ---------------------------------------------------------------------------
// Kernel: exclusive prefix over chunks — batched loads for MLP
// ---------------------------------------------------------------------------
__global__ __launch_bounds__(256)
void scan_prefix()
{
    int id  = blockIdx.x * 256 + threadIdx.x;   // 0 .. B*K*D-1
    int b   = id >> 14;
    int rem = id & 16383;
    float* base = g_S + (size_t)b*NCH*KK*DD + rem;

    float v[NCH];
    #pragma unroll
    for (int c = 0; c < NCH; ++c)
        v[c] = base[(size_t)c*KK*DD];
    float run = 0.f;
    #pragma unroll
    for (int c = 0; c < NCH; ++c) {
        float t = v[c];
        base[(size_t)c*KK*DD] = run;
        run += t;
    }
}

// ---------------------------------------------------------------------------
// Kernel: apply scan, 2 d-columns per thread -> g_reth (fp16).
// grid = (DD/256, NCH, BB), 128 threads.
// ---------------------------------------------------------------------------
__global__ __launch_bounds__(128)
void scan_apply()
{
    int d2 = blockIdx.x * 128 + threadIdx.x;
    int c = blockIdx.y;
    int b = blockIdx.z;
    __shared__ float cks[LC*KK];
    __shared__ float cqs[LC*KK];

    int base_t = b*LL + c*LC;
    for (int i = threadIdx.x; i < LC*KK; i += 128) {
        cks[i] = g_ck[base_t*KK + i];
        cqs[i] = g_cq[base_t*KK + i];
    }
    __syncthreads();

    float sx[KK], sy[KK];
    const float2* Sp = (const float2*)(g_S + ((size_t)(b*NCH + c)*KK)*DD) + d2;
    #pragma unroll
    for (int k = 0; k < KK; ++k) {
        float2 s = Sp[(size_t)k*(DD/2)];
        sx[k] = s.x; sy[k] = s.y;
    }

    const __half2* vp = (const __half2*)(g_valh + (size_t)base_t*DD) + d2;
    __half2*       rp = (__half2*)(g_reth + (size_t)base_t*DD) + d2;
    for (int t = 0; t < LC; ++t) {
        float2 v = __half22float2(vp[(size_t)t*(DD/2)]);
        float ax = 0.f, ay = 0.f;
        #pragma unroll
        for (int k = 0; k < KK; ++k) {
            float ckv = cks[t*KK + k];
            float cqv = cqs[t*KK + k];
            sx[k] += v.x * ckv;
            sy[k] += v.y * ckv;
            ax    += cqv * sx[k];
            ay    += cqv * sy[k];
        }
        rp[(size_t)t*(DD/2)] = __floats2half2_rn(ax * 0.25f, ay * 0.25f);
    }
}

// ---------------------------------------------------------------------------
// Kernel: LayerNorm on g_reth (fp16 in), fused fp16 panel output
// ---------------------------------------------------------------------------
__global__ __launch_bounds__(256)
void layernorm_conv(const float* __restrict__ gam, const float* __restrict__ bet)
{
    int t = blockIdx.x;
    const __half2* row = (const __half2*)(g_reth + (size_t)t*DD);
    __shared__ float sh[DD];
    __shared__ float ws[8], wq[8];
    __shared__ float s_mean, s_rstd;

    int tid  = threadIdx.x;
    int lane = tid & 31;
    int wid  = tid >> 5;

    // 256 threads * 2 half2 = 1024 values
    float2 a = __half22float2(row[tid*2]);
    float2 b = __half22float2(row[tid*2 + 1]);
    sh[tid*4+0] = a.x; sh[tid*4+1] = a.y; sh[tid*4+2] = b.x; sh[tid*4+3] = b.y;
    float s = a.x + a.y + b.x + b.y;
    float q = a.x*a.x + a.y*a.y + b.x*b.x + b.y*b.y;
    #pragma unroll
    for (int off = 16; off; off >>= 1) {
        s += __shfl_xor_sync(0xffffffffu, s, off);
        q += __shfl_xor_sync(0xffffffffu, q, off);
    }
    if (lane == 0) { ws[wid] = s; wq[wid] = q; }
    __syncthreads();
    if (tid == 0) {
        float S = 0.f, Q = 0.f;
        #pragma unroll
        for (int i = 0; i < 8; ++i) { S += ws[i]; Q += wq[i]; }
        float m   = S / (float)DD;
        float var = Q / (float)DD - m*m;
        s_mean = m;
        s_rstd = rsqrtf(var + 1e-5f);
    }
    __syncthreads();
    float m = s_mean, r = s_rstd;

    int d0 = tid * 4;
    float nv[4];
    #pragma unroll
    for (int i = 0; i < 4; ++i) {
        int d = d0 + i;
        nv[i] = (sh[d] - m) * r * gam[d] + bet[d];
    }
    int c8    = d0 >> 6;
    int inrow = ((d0 & 63) * 2) ^ ((t & 7) << 4);
    size_t byteoff = ((size_t)c8 * BL + t) * 128 + inrow;
    *(uint2*)((char*)g_ahi + byteoff) = make_uint2(pk2h(nv[0],nv[1]), pk2h(nv[2],nv[3]));
}

// ---------------------------------------------------------------------------
extern "C" void kernel_launch(void* const* d_in, const int* in_sizes, int n_in,
                              void* d_out, int out_size)
{
    const float* x       = (const float*)d_in[0];
    const float* Wv      = (const float*)d_in[1];
    const float* bv      = (const float*)d_in[2];
    const float* Wck     = (const float*)d_in[3];
    const float* bck     = (const float*)d_in[4];
    const float* Wc      = (const float*)d_in[5];
    const float* bc      = (const float*)d_in[6];
    const float* Wcq     = (const float*)d_in[7];
    const float* bcq     = (const float*)d_in[8];
    const float* ln_g    = (const float*)d_in[9];
    const float* ln_b    = (const float*)d_in[10];
    const float* Wo      = (const float*)d_in[11];
    const float* bo      = (const float*)d_in[12];
    const float* pos_key = (const float*)d_in[13];
    float* out = (float*)d_out;

    cudaFuncSetAttribute(mma_gemm<0>, cudaFuncAttributeMaxDynamicSharedMemorySize, GSMEM);
    cudaFuncSetAttribute(mma_gemm<1>, cudaFuncAttributeMaxDynamicSharedMemorySize, GSMEM);

    // both weight panels in one launch (off critical path)
    conv_w<<<2*CONVW_BLOCKS, 256>>>(Wv, Wo);

    // proj + fused x->panel conversion
    proj_kernel<<<BL/PT, 256>>>(x, Wck, bck, Wcq, bcq, Wc, bc, pos_key);

    // value = x @ Wv^T + bv  (written as fp16 into g_valh)
    mma_gemm<0><<<dim3(DD/256, BL/128), 256, GSMEM>>>(bv, nullptr, nullptr);

    // chunked causal scan (2 d-columns per thread)
    {
        dim3 grid(DD/256, NCH, BB);
        scan_partial<<<grid, 128>>>();
        scan_prefix<<<(BB*KK*DD)/256, 256>>>();
        scan_apply<<<grid, 128>>>();
    }

    // LayerNorm + fused fp16 conversion into A panel
    layernorm_conv<<<BL, 256>>>(ln_g, ln_b);

    // out = x + normed @ Wo^T + bo
    mma_gemm<1><<<dim3(DD/256, BL/128), 256, GSMEM>>>(bo, x, out);
}

// round 14
// speedup vs baseline: 1.1638x; 1.0174x over previous
#include <cuda_runtime.h>
#include <cuda_bf16.h>
#include <cuda_fp16.h>
#include <math.h>

// Problem constants
#define BB   4
#define LL   2048
#define DD   1024
#define KK   16
#define BL   (BB*LL)        // 8192 tokens
#define NCH  32             // scan chunks
#define LC   (LL/NCH)       // 64 tokens per chunk

// ---------------------------------------------------------------------------
// Scratch (no allocation allowed -> __device__ globals)
// ---------------------------------------------------------------------------
__device__ __half g_valh[BL*DD];            // 16 MB (value, fp16)
__device__ __half g_reth[BL*DD];            // 16 MB (retrieved, fp16, pre-LN)
__device__ float g_ck   [BL*KK];
__device__ float g_cq   [BL*KK];
__device__ float g_S    [BB*NCH*KK*DD];     // 8 MB chunk states

// fp16 operand panels, chunk-major, swizzled (cell ^ (row&7)) layout.
__device__ uint4 g_ahi[(16*8192*128)/16];   // 16 MB (x, later normed)
__device__ uint4 g_bhi[(16*1024*128)/16];   // 2 MB  (Wv)
__device__ uint4 g_bhi2[(16*1024*128)/16];  // 2 MB  (Wo)

// ---------------------------------------------------------------------------
// PTX helpers (base sm_90/sm_80 features only — target is plain sm_100!)
// ---------------------------------------------------------------------------
__device__ __forceinline__ unsigned smem_u32(const void* p) {
    unsigned a;
    asm("{ .reg .u64 t; cvta.to.shared.u64 t, %1; cvt.u32.u64 %0, t; }" : "=r"(a) : "l"(p));
    return a;
}

#define MBAR_INIT(addr, cnt) \
    asm volatile("mbarrier.init.shared.b64 [%0], %1;" :: "r"(addr), "r"(cnt) : "memory")
#define MBAR_INVAL(addr) \
    asm volatile("mbarrier.inval.shared.b64 [%0];" :: "r"(addr) : "memory")
#define MBAR_EXPECT_TX(addr, bytes) \
    asm volatile("mbarrier.arrive.expect_tx.shared.b64 _, [%0], %1;" :: "r"(addr), "r"(bytes) : "memory")
#define MBAR_ARRIVE(addr) \
    asm volatile("mbarrier.arrive.shared.b64 _, [%0];" :: "r"(addr) : "memory")

#define MBAR_WAIT(addr, par) do {                                              \
    unsigned _m = (addr), _p = (par), _d;                                      \
    asm volatile("{\n\t.reg .pred p;\n\t"                                      \
        "mbarrier.try_wait.parity.acquire.cta.shared::cta.b64 p, [%1], %2;\n\t"\
        "selp.b32 %0, 1, 0, p;\n\t}"                                           \
        : "=r"(_d) : "r"(_m), "r"(_p) : "memory");                             \
    if (!_d) {                                                                 \
        asm volatile("{\n\t.reg .pred P1;\n\t"                                 \
            "W%=:\n\t"                                                         \
            "mbarrier.try_wait.parity.acquire.cta.shared::cta.b64 P1, [%0], %1, 0x989680;\n\t" \
            "@P1 bra.uni D%=;\n\t"                                             \
            "bra.uni W%=;\n\t"                                                 \
            "D%=:\n\t}" :: "r"(_m), "r"(_p) : "memory");                       \
    }                                                                          \
} while (0)

#define CP_BULK(dst, src, bytes, mbar) \
    asm volatile("cp.async.bulk.shared::cluster.global.mbarrier::complete_tx::bytes [%0], [%1], %2, [%3];" \
        :: "r"(dst), "l"(src), "r"(bytes), "r"(mbar) : "memory")

#define FENCE_PROXY() asm volatile("fence.proxy.async.shared::cta;" ::: "memory")

#define LDSM_X4(r0, r1, r2, r3, addr) \
    asm volatile("ldmatrix.sync.aligned.m8n8.x4.shared.b16 {%0,%1,%2,%3}, [%4];" \
        : "=r"(r0), "=r"(r1), "=r"(r2), "=r"(r3) : "r"(addr))

__device__ __forceinline__ void mma16816h(float* d, const unsigned* a, const unsigned* b) {
    asm volatile("mma.sync.aligned.m16n8k16.row.col.f32.f16.f16.f32 "
        "{%0,%1,%2,%3}, {%4,%5,%6,%7}, {%8,%9}, {%0,%1,%2,%3};"
        : "+f"(d[0]), "+f"(d[1]), "+f"(d[2]), "+f"(d[3])
        : "r"(a[0]), "r"(a[1]), "r"(a[2]), "r"(a[3]), "r"(b[0]), "r"(b[1]));
}

// pack 2 floats -> fp16x2 bits
__device__ __forceinline__ unsigned pk2h(float x, float y) {
    __half2 h = __floats2half2_rn(x, y);
    return *reinterpret_cast<unsigned*>(&h);
}

// ---------------------------------------------------------------------------
// Kernel: conv_w — Wv and Wo (1024x1024 fp32 each) -> fp16 B panels.
// Single launch; blockIdx.x >= half selects Wo.
// ---------------------------------------------------------------------------
#define CONVW_BLOCKS ((DD*128)/256)
__global__ __launch_bounds__(256)
void conv_w(const float* __restrict__ w0, const float* __restrict__ w1)
{
    int bx = blockIdx.x;
    int which = bx >= CONVW_BLOCKS;
    const float* src = which ? w1 : w0;
    uint4* dst = which ? g_bhi2 : g_bhi;
    int id = (bx - which*CONVW_BLOCKS) * 256 + threadIdx.x;  // 0 .. 1024*128-1

    int n = id >> 7;
    int cc = id & 127;
    int c = cc >> 3, cell = cc & 7;
    int k0 = c * 64 + cell * 8;

    const float4* s = (const float4*)(src + (size_t)n * DD + k0);
    float4 a = s[0], b = s[1];

    uint4 H = make_uint4(pk2h(a.x,a.y), pk2h(a.z,a.w), pk2h(b.x,b.y), pk2h(b.z,b.w));
    size_t off16 = ((size_t)c * DD + n) * 8 + (cell ^ (n & 7));
    dst[off16] = H;
}

// ---------------------------------------------------------------------------
// Kernel: mma_gemm — C[8192x1024] = A @ W^T (+bias, optionally +X residual)
// fp16 single-product (fp32 accum). 4-stage cp.async.bulk pipeline, scoped
// mbarrier flow control, register double-buffered ldmatrix.
// CTA tile 128x256, 8 warps (2x4), warp tile 64x64.
// MODE 0: C = g_valh (fp16), B = Wv panel. MODE 1: C = Cout += X, B = Wo panel.
// ---------------------------------------------------------------------------
#define TILE_A   16384                  // 128x64 fp16
#define TILE_BB  32768                  // 256x64 fp16
#define STG      (TILE_A + TILE_BB)     // 48 KB
#define KBLK     16
#define NSTAGE   4
#define GSMEM    (1024 + NSTAGE*STG)    // 197632
#define NWARP    8

template<int MODE>
__global__ __launch_bounds__(256, 1)
void mma_gemm(const float* __restrict__ bias, const float* __restrict__ X,
              float* __restrict__ Cout)
{
    extern __shared__ char smem[];
    unsigned sb = smem_u32(smem);
    int tid = threadIdx.x, lane = tid & 31, wid = tid >> 5;
    int wm = wid & 1, wn = wid >> 1;          // 2 x 4 warp grid, 64x64 tiles
    int bn = blockIdx.x * 256, bm = blockIdx.y * 128;

    if (tid == 0) {
        #pragma unroll
        for (int s = 0; s < NSTAGE; ++s) {
            MBAR_INIT(sb + 8  + 16*s, 1);
            MBAR_INIT(sb + 16 + 16*s, NWARP);
        }
        FENCE_PROXY();
    }
    __syncthreads();

    const char* pA = (const char*)g_ahi;
    const char* pB = (MODE == 0) ? (const char*)g_bhi : (const char*)g_bhi2;

    auto issue = [&](int kb, int s) {
        unsigned st = sb + 1024 + s * STG;
        unsigned fm = sb + 8 + 16*s;
        size_t aoff = ((size_t)kb * BL + bm) * 128;
        size_t boff = ((size_t)kb * DD + bn) * 128;
        MBAR_EXPECT_TX(fm, STG);
        CP_BULK(st,          pA + aoff, TILE_A,  fm);
        CP_BULK(st + TILE_A, pB + boff, TILE_BB, fm);
    };
    if (tid == 0) {
        #pragma unroll
        for (int s = 0; s < NSTAGE - 1; ++s) issue(s, s);
    }

    float acc[4][8][4];
    #pragma unroll
    for (int i = 0; i < 4; ++i)
        #pragma unroll
        for (int j = 0; j < 8; ++j)
            #pragma unroll
            for (int q = 0; q < 4; ++q) acc[i][j][q] = 0.f;

    int rl = (lane & 7) + ((lane >> 3) & 1) * 8;
    int cs = lane >> 4;

    int rA[4], sA[4], rB[4], sB[4];
    #pragma unroll
    for (int i = 0; i < 4; ++i) { int r = wm*64 + i*16 + rl; rA[i] = r*128; sA[i] = r & 7; }
    #pragma unroll
    for (int j = 0; j < 4; ++j) { int r = wn*64 + j*16 + rl; rB[j] = r*128; sB[j] = r & 7; }

    unsigned opA[2][16], opB[2][16];

    auto load_ops = [&](unsigned bA, unsigned bBp, int ks, unsigned* A, unsigned* B) {
        int cc = ks * 2 + cs;
        #pragma unroll
        for (int i = 0; i < 4; ++i) {
            unsigned off = rA[i] + ((cc ^ sA[i]) << 4);
            LDSM_X4(A[i*4+0], A[i*4+1], A[i*4+2], A[i*4+3], bA + off);
        }
        #pragma unroll
        for (int j = 0; j < 4; ++j) {
            unsigned off = rB[j] + ((cc ^ sB[j]) << 4);
            unsigned r0, r1, r2, r3;
            LDSM_X4(r0, r1, r2, r3, bBp + off);
            B[j*4+0] = r0; B[j*4+1] = r2; B[j*4+2] = r1; B[j*4+3] = r3;
        }
    };

    auto do_mma = [&](const unsigned* A, const unsigned* B) {
        #pragma unroll
        for (int jt = 0; jt < 4; ++jt)
            #pragma unroll
            for (int h = 0; h < 2; ++h) {
                const unsigned* Bf = B + jt*4 + h*2;
                #pragma unroll
                for (int i = 0; i < 4; ++i)
                    mma16816h(acc[i][jt*2+h], A + i*4, Bf);
            }
    };

    for (int kb = 0; kb < KBLK; ++kb) {
        int s  = kb % NSTAGE;
        int ph = (kb / NSTAGE) & 1;
        MBAR_WAIT(sb + 8 + 16*s, ph);
        unsigned st = sb + 1024 + s * STG;
        unsigned bA = st, bBp = st + TILE_A;

        load_ops(bA, bBp, 0, opA[0], opB[0]);
        #pragma unroll
        for (int ks = 0; ks < 4; ++ks) {
            int cur = ks & 1;
            if (ks < 3) load_ops(bA, bBp, ks + 1, opA[cur^1], opB[cur^1]);
            do_mma(opA[cur], opB[cur]);
        }

        if (lane == 0) MBAR_ARRIVE(sb + 16 + 16*s);
        if (tid == 0 && kb + NSTAGE - 1 < KBLK) {
            MBAR_WAIT(sb + 16 + 16*s, ph);
            issue(kb + NSTAGE - 1, (kb + NSTAGE - 1) % NSTAGE);
        }
    }

    // epilogue: warp writes its 64x64 sub-tile
    #pragma unroll
    for (int i = 0; i < 4; ++i) {
        int r0 = bm + wm*64 + i*16 + (lane >> 2);
        #pragma unroll
        for (int j = 0; j < 8; ++j) {
            int col = bn + wn*64 + j*8 + (lane & 3)*2;
            float2 b2 = *(const float2*)(bias + col);
            float2 v0 = make_float2(acc[i][j][0] + b2.x, acc[i][j][1] + b2.y);
            float2 v1 = make_float2(acc[i][j][2] + b2.x, acc[i][j][3] + b2.y);
            if (MODE == 1) {
                float2 x0 = *(const float2*)(X + (size_t)r0*DD + col);
                float2 x1 = *(const float2*)(X + (size_t)(r0+8)*DD + col);
                v0.x += x0.x; v0.y += x0.y;
                v1.x += x1.x; v1.y += x1.y;
                *(float2*)(Cout + (size_t)r0*DD + col)     = v0;
                *(float2*)(Cout + (size_t)(r0+8)*DD + col) = v1;
            } else {
                *(__half2*)(&g_valh[(size_t)r0*DD + col])     = __floats2half2_rn(v0.x, v0.y);
                *(__half2*)(&g_valh[(size_t)(r0+8)*DD + col]) = __floats2half2_rn(v1.x, v1.y);
            }
        }
    }

    __syncthreads();
    if (tid == 0) {
        #pragma unroll
        for (int s = 0; s < NSTAGE; ++s) {
            MBAR_INVAL(sb + 8  + 16*s);
            MBAR_INVAL(sb + 16 + 16*s);
        }
    }
}

// ---------------------------------------------------------------------------
// Kernel: proj — content key/query + combiner for 8 tokens per block,
// FUSED with x -> fp16 A-panel conversion (reads x once).
// ---------------------------------------------------------------------------
#define PT 8
__global__ __launch_bounds__(256)
void proj_kernel(const float* __restrict__ x,
                 const float* __restrict__ Wck, const float* __restrict__ bck,
                 const float* __restrict__ Wcq, const float* __restrict__ bcq,
                 const float* __restrict__ Wc,  const float* __restrict__ bc,
                 const float* __restrict__ pos_key)
{
    int t0   = blockIdx.x * PT;
    int tid  = threadIdx.x;
    int lane = tid & 31;
    int warp = tid >> 5;

    __shared__ float xs[PT][DD];
    __shared__ float dots[2][PT][16];
    __shared__ float pos_s[PT][16];

    #pragma unroll
    for (int i = tid; i < PT*DD/4; i += 256)
        ((float4*)&xs[0][0])[i] = ((const float4*)(x + (size_t)t0*DD))[i];
    if (tid < PT*16) {
        int tt = tid >> 4, k = tid & 15;
        int l = (t0 + tt) & (LL-1);
        pos_s[tt][k] = pos_key[l*KK + k];
    }
    __syncthreads();

    // --- fused conv: emit fp16 panel rows ---
    {
        int tt   = tid >> 5;
        int t    = t0 + tt;
        int cell = lane & 7;
        #pragma unroll
        for (int q = 0; q < 4; ++q) {
            int c  = (lane >> 3) + q*4;
            int k0 = c*64 + cell*8;
            const float* v = &xs[tt][k0];
            uint4 H = make_uint4(pk2h(v[0],v[1]), pk2h(v[2],v[3]),
                                 pk2h(v[4],v[5]), pk2h(v[6],v[7]));
            size_t off16 = ((size_t)c * BL + t) * 8 + (cell ^ (t & 7));
            g_ahi[off16] = H;
        }
    }

    // --- 32 dot products; each warp does 4 (sequential — keeps regs low) ---
    #pragma unroll 1
    for (int oo = 0; oo < 4; ++oo) {
        int o = warp + oo*8;
        const float* W = (o < 16) ? (Wck + (size_t)o*DD) : (Wcq + (size_t)(o-16)*DD);
        float bias_o   = (o < 16) ? bck[o] : bcq[o-16];
        float wreg[32];
        #pragma unroll
        for (int i = 0; i < 32; ++i) wreg[i] = W[lane + 32*i];
        #pragma unroll
        for (int t = 0; t < PT; ++t) {
            float s = 0.f;
            #pragma unroll
            for (int i = 0; i < 32; ++i) s += wreg[i] * xs[t][lane + 32*i];
            #pragma unroll
            for (int off = 16; off; off >>= 1)
                s += __shfl_xor_sync(0xffffffffu, s, off);
            if (lane == 0)
                dots[o >> 4][t][o & 15] = s + bias_o;
        }
    }
    __syncthreads();

    // --- normalize + combiner + normalize ---
    {
        int t    = warp;
        int path = lane >> 4;
        int l16  = lane & 15;

        float v = dots[path][t][l16];
        float ss = v*v;
        #pragma unroll
        for (int off = 8; off; off >>= 1)
            ss += __shfl_xor_sync(0xffffffffu, ss, off, 16);
        float cnv = v / fmaxf(sqrtf(ss), 1e-12f);

        float s = bc[l16];
        #pragma unroll
        for (int j = 0; j < 16; ++j) {
            float cj = __shfl_sync(0xffffffffu, cnv, j, 16);
            s += Wc[l16*32 + j]      * pos_s[t][j];
            s += Wc[l16*32 + 16 + j] * cj;
        }
        s = tanhf(s);
        float sq = s*s;
        #pragma unroll
        for (int off = 8; off; off >>= 1)
            sq += __shfl_xor_sync(0xffffffffu, sq, off, 16);
        float outv = s / fmaxf(sqrtf(sq), 1e-12f);
        float* dst = (path == 0) ? g_ck : g_cq;
        dst[(t0 + t)*KK + l16] = outv;
    }
}

// ---------------------------------------------------------------------------
// Kernel: per-chunk partial state, 2 d-columns per thread, t-loop unrolled x4
// with front-batched loads (MLP=4). grid = (DD/256, NCH, BB), 128 threads.
// ---------------------------------------------------------------------------
__global__ __launch_bounds__(128)
void scan_partial()
{
    int d2 = blockIdx.x * 128 + threadIdx.x;   // 0..511 -> pair (2*d2, 2*d2+1)
    int c = blockIdx.y;
    int b = blockIdx.z;
    __shared__ float cks[LC*KK];

    int base_t = b*LL + c*LC;
    for (int i = threadIdx.x; i < LC*KK; i += 128)
        cks[i] = g_ck[base_t*KK + i];
    __syncthreads();

    float sx[KK], sy[KK];
    #pragma unroll
    for (int k = 0; k < KK; ++k) { sx[k] = 0.f; sy[k] = 0.f; }

    const __half2* vp = (const __half2*)(g_valh + (size_t)base_t*DD) + d2;
    #pragma unroll 1
    for (int t = 0; t < LC; t += 4) {
        float2 v[4];
        #pragma unroll
        for (int u = 0; u < 4; ++u)
            v[u] = __half22float2(vp[(size_t)(t+u)*(DD/2)]);
        #pragma unroll
        for (int u = 0; u < 4; ++u) {
            #pragma unroll
            for (int k = 0; k < KK; ++k) {
                float ckv = cks[(t+u)*KK + k];
                sx[k] += v[u].x * ckv;
                sy[k] += v[u].y * ckv;
            }
        }
    }
    float2* Sp = (float2*)(g_S + ((size_t)(b*NCH + c)*KK)*DD) + d2;
    #pragma unroll
    for (int k = 0; k < KK; ++k)
        Sp[(size_t)k*(DD/2)] = make_float2(sx[k], sy[k]);
}

// ---------------------------------------------------------------------------
// Kernel: exclusive prefix over chunks — batched loads for MLP
// ---------------------------------------------------------------------------
__global__ __launch_bounds__(256)
void scan_prefix()
{
    int id  = blockIdx.x * 256 + threadIdx.x;   // 0 .. B*K*D-1
    int b   = id >> 14;
    int rem = id & 16383;
    float* base = g_S + (size_t)b*NCH*KK*DD + rem;

    float v[NCH];
    #pragma unroll
    for (int c = 0; c < NCH; ++c)
        v[c] = base[(size_t)c*KK*DD];
    float run = 0.f;
    #pragma unroll
    for (int c = 0; c < NCH; ++c) {
        float t = v[c];
        base[(size_t)c*KK*DD] = run;
        run += t;
    }
}

// ---------------------------------------------------------------------------
// Kernel: apply scan, 2 d-columns per thread, t-loop unrolled x4 with
// front-batched loads -> g_reth (fp16). grid = (DD/256, NCH, BB), 128 thr.
// ---------------------------------------------------------------------------
__global__ __launch_bounds__(128)
void scan_apply()
{
    int d2 = blockIdx.x * 128 + threadIdx.x;
    int c = blockIdx.y;
    int b = blockIdx.z;
    __shared__ float cks[LC*KK];
    __shared__ float cqs[LC*KK];

    int base_t = b*LL + c*LC;
    for (int i = threadIdx.x; i < LC*KK; i += 128) {
        cks[i] = g_ck[base_t*KK + i];
        cqs[i] = g_cq[base_t*KK + i];
    }
    __syncthreads();

    float sx[KK], sy[KK];
    const float2* Sp = (const float2*)(g_S + ((size_t)(b*NCH + c)*KK)*DD) + d2;
    #pragma unroll
    for (int k = 0; k < KK; ++k) {
        float2 s = Sp[(size_t)k*(DD/2)];
        sx[k] = s.x; sy[k] = s.y;
    }

    const __half2* vp = (const __half2*)(g_valh + (size_t)base_t*DD) + d2;
    __half2*       rp = (__half2*)(g_reth + (size_t)base_t*DD) + d2;
    #pragma unroll 1
    for (int t = 0; t < LC; t += 4) {
        float2 v[4];
        #pragma unroll
        for (int u = 0; u < 4; ++u)
            v[u] = __half22float2(vp[(size_t)(t+u)*(DD/2)]);
        #pragma unroll
        for (int u = 0; u < 4; ++u) {
            float ax = 0.f, ay = 0.f;
            #pragma unroll
            for (int k = 0; k < KK; ++k) {
                float ckv = cks[(t+u)*KK + k];
                float cqv = cqs[(t+u)*KK + k];
                sx[k] += v[u].x * ckv;
                sy[k] += v[u].y * ckv;
                ax    += cqv * sx[k];
                ay    += cqv * sy[k];
            }
            rp[(size_t)(t+u)*(DD/2)] = __floats2half2_rn(ax * 0.25f, ay * 0.25f);
        }
    }
}

// ---------------------------------------------------------------------------
// Kernel: LayerNorm on g_reth (fp16 in), fused fp16 panel output
// ---------------------------------------------------------------------------
__global__ __launch_bounds__(256)
void layernorm_conv(const float* __restrict__ gam, const float* __restrict__ bet)
{
    int t = blockIdx.x;
    const __half2* row = (const __half2*)(g_reth + (size_t)t*DD);
    __shared__ float sh[DD];
    __shared__ float ws[8], wq[8];
    __shared__ float s_mean, s_rstd;

    int tid  = threadIdx.x;
    int lane = tid & 31;
    int wid  = tid >> 5;

    // 256 threads * 2 half2 = 1024 values
    float2 a = __half22float2(row[tid*2]);
    float2 b = __half22float2(row[tid*2 + 1]);
    sh[tid*4+0] = a.x; sh[tid*4+1] = a.y; sh[tid*4+2] = b.x; sh[tid*4+3] = b.y;
    float s = a.x + a.y + b.x + b.y;
    float q = a.x*a.x + a.y*a.y + b.x*b.x + b.y*b.y;
    #pragma unroll
    for (int off = 16; off; off >>= 1) {
        s += __shfl_xor_sync(0xffffffffu, s, off);
        q += __shfl_xor_sync(0xffffffffu, q, off);
    }
    if (lane == 0) { ws[wid] = s; wq[wid] = q; }
    __syncthreads();
    if (tid == 0) {
        float S = 0.f, Q = 0.f;
        #pragma unroll
        for (int i = 0; i < 8; ++i) { S += ws[i]; Q += wq[i]; }
        float m   = S / (float)DD;
        float var = Q / (float)DD - m*m;
        s_mean = m;
        s_rstd = rsqrtf(var + 1e-5f);
    }
    __syncthreads();
    float m = s_mean, r = s_rstd;

    int d0 = tid * 4;
    float nv[4];
    #pragma unroll
    for (int i = 0; i < 4; ++i) {
        int d = d0 + i;
        nv[i] = (sh[d] - m) * r * gam[d] + bet[d];
    }
    int c8    = d0 >> 6;
    int inrow = ((d0 & 63) * 2) ^ ((t & 7) << 4);
    size_t byteoff = ((size_t)c8 * BL + t) * 128 + inrow;
    *(uint2*)((char*)g_ahi + byteoff) = make_uint2(pk2h(nv[0],nv[1]), pk2h(nv[2],nv[3]));
}

// ---------------------------------------------------------------------------
extern "C" void kernel_launch(void* const* d_in, const int* in_sizes, int n_in,
                              void* d_out, int out_size)
{
    const float* x       = (const float*)d_in[0];
    const float* Wv      = (const float*)d_in[1];
    const float* bv      = (const float*)d_in[2];
    const float* Wck     = (const float*)d_in[3];
    const float* bck     = (const float*)d_in[4];
    const float* Wc      = (const float*)d_in[5];
    const float* bc      = (const float*)d_in[6];
    const float* Wcq     = (const float*)d_in[7];
    const float* bcq     = (const float*)d_in[8];
    const float* ln_g    = (const float*)d_in[9];
    const float* ln_b    = (const float*)d_in[10];
    const float* Wo      = (const float*)d_in[11];
    const float* bo      = (const float*)d_in[12];
    const float* pos_key = (const float*)d_in[13];
    float* out = (float*)d_out;

    cudaFuncSetAttribute(mma_gemm<0>, cudaFuncAttributeMaxDynamicSharedMemorySize, GSMEM);
    cudaFuncSetAttribute(mma_gemm<1>, cudaFuncAttributeMaxDynamicSharedMemorySize, GSMEM);

    // both weight panels in one launch (off critical path)
    conv_w<<<2*CONVW_BLOCKS, 256>>>(Wv, Wo);

    // proj + fused x->panel conversion
    proj_kernel<<<BL/PT, 256>>>(x, Wck, bck, Wcq, bcq, Wc, bc, pos_key);

    // value = x @ Wv^T + bv  (written as fp16 into g_valh)
    mma_gemm<0><<<dim3(DD/256, BL/128), 256, GSMEM>>>(bv, nullptr, nullptr);

    // chunked causal scan (2 d-columns per thread, t unrolled x4)
    {
        dim3 grid(DD/256, NCH, BB);
        scan_partial<<<grid, 128>>>();
        scan_prefix<<<(BB*KK*DD)/256, 256>>>();
        scan_apply<<<grid, 128>>>();
    }

    // LayerNorm + fused fp16 conversion into A panel
    layernorm_conv<<<BL, 256>>>(ln_g, ln_b);

    // out = x + normed @ Wo^T + bo
    mma_gemm<1><<<dim3(DD/256, BL/128), 256, GSMEM>>>(bo, x, out);
}

// round 15
// speedup vs baseline: 1.1820x; 1.0156x over previous
#include <cuda_runtime.h>
#include <cuda_bf16.h>
#include <cuda_fp16.h>
#include <math.h>

// Problem constants
#define BB   4
#define LL   2048
#define DD   1024
#define KK   16
#define BL   (BB*LL)        // 8192 tokens
#define NCH  64             // scan chunks (raised for occupancy)
#define LC   (LL/NCH)       // 32 tokens per chunk

// ---------------------------------------------------------------------------
// Scratch (no allocation allowed -> __device__ globals)
// ---------------------------------------------------------------------------
__device__ __half g_valh[BL*DD];            // 16 MB (value, fp16)
__device__ __half g_reth[BL*DD];            // 16 MB (retrieved, fp16, pre-LN)
__device__ float g_ck   [BL*KK];
__device__ float g_cq   [BL*KK];
__device__ float g_S    [BB*NCH*KK*DD];     // 16 MB chunk states

// fp16 operand panels, chunk-major, swizzled (cell ^ (row&7)) layout.
__device__ uint4 g_ahi[(16*8192*128)/16];   // 16 MB (x, later normed)
__device__ uint4 g_bhi[(16*1024*128)/16];   // 2 MB  (Wv)
__device__ uint4 g_bhi2[(16*1024*128)/16];  // 2 MB  (Wo)

// ---------------------------------------------------------------------------
// PTX helpers (base sm_90/sm_80 features only — target is plain sm_100!)
// ---------------------------------------------------------------------------
__device__ __forceinline__ unsigned smem_u32(const void* p) {
    unsigned a;
    asm("{ .reg .u64 t; cvta.to.shared.u64 t, %1; cvt.u32.u64 %0, t; }" : "=r"(a) : "l"(p));
    return a;
}

#define MBAR_INIT(addr, cnt) \
    asm volatile("mbarrier.init.shared.b64 [%0], %1;" :: "r"(addr), "r"(cnt) : "memory")
#define MBAR_INVAL(addr) \
    asm volatile("mbarrier.inval.shared.b64 [%0];" :: "r"(addr) : "memory")
#define MBAR_EXPECT_TX(addr, bytes) \
    asm volatile("mbarrier.arrive.expect_tx.shared.b64 _, [%0], %1;" :: "r"(addr), "r"(bytes) : "memory")
#define MBAR_ARRIVE(addr) \
    asm volatile("mbarrier.arrive.shared.b64 _, [%0];" :: "r"(addr) : "memory")

#define MBAR_WAIT(addr, par) do {                                              \
    unsigned _m = (addr), _p = (par), _d;                                      \
    asm volatile("{\n\t.reg .pred p;\n\t"                                      \
        "mbarrier.try_wait.parity.acquire.cta.shared::cta.b64 p, [%1], %2;\n\t"\
        "selp.b32 %0, 1, 0, p;\n\t}"                                           \
        : "=r"(_d) : "r"(_m), "r"(_p) : "memory");                             \
    if (!_d) {                                                                 \
        asm volatile("{\n\t.reg .pred P1;\n\t"                                 \
            "W%=:\n\t"                                                         \
            "mbarrier.try_wait.parity.acquire.cta.shared::cta.b64 P1, [%0], %1, 0x989680;\n\t" \
            "@P1 bra.uni D%=;\n\t"                                             \
            "bra.uni W%=;\n\t"                                                 \
            "D%=:\n\t}" :: "r"(_m), "r"(_p) : "memory");                       \
    }                                                                          \
} while (0)

#define CP_BULK(dst, src, bytes, mbar) \
    asm volatile("cp.async.bulk.shared::cluster.global.mbarrier::complete_tx::bytes [%0], [%1], %2, [%3];" \
        :: "r"(dst), "l"(src), "r"(bytes), "r"(mbar) : "memory")

#define FENCE_PROXY() asm volatile("fence.proxy.async.shared::cta;" ::: "memory")

#define LDSM_X4(r0, r1, r2, r3, addr) \
    asm volatile("ldmatrix.sync.aligned.m8n8.x4.shared.b16 {%0,%1,%2,%3}, [%4];" \
        : "=r"(r0), "=r"(r1), "=r"(r2), "=r"(r3) : "r"(addr))

__device__ __forceinline__ void mma16816h(float* d, const unsigned* a, const unsigned* b) {
    asm volatile("mma.sync.aligned.m16n8k16.row.col.f32.f16.f16.f32 "
        "{%0,%1,%2,%3}, {%4,%5,%6,%7}, {%8,%9}, {%0,%1,%2,%3};"
        : "+f"(d[0]), "+f"(d[1]), "+f"(d[2]), "+f"(d[3])
        : "r"(a[0]), "r"(a[1]), "r"(a[2]), "r"(a[3]), "r"(b[0]), "r"(b[1]));
}

// pack 2 floats -> fp16x2 bits
__device__ __forceinline__ unsigned pk2h(float x, float y) {
    __half2 h = __floats2half2_rn(x, y);
    return *reinterpret_cast<unsigned*>(&h);
}

// ---------------------------------------------------------------------------
// Kernel: conv_w — Wv and Wo (1024x1024 fp32 each) -> fp16 B panels.
// Single launch; blockIdx.x >= half selects Wo.
// ---------------------------------------------------------------------------
#define CONVW_BLOCKS ((DD*128)/256)
__global__ __launch_bounds__(256)
void conv_w(const float* __restrict__ w0, const float* __restrict__ w1)
{
    int bx = blockIdx.x;
    int which = bx >= CONVW_BLOCKS;
    const float* src = which ? w1 : w0;
    uint4* dst = which ? g_bhi2 : g_bhi;
    int id = (bx - which*CONVW_BLOCKS) * 256 + threadIdx.x;  // 0 .. 1024*128-1

    int n = id >> 7;
    int cc = id & 127;
    int c = cc >> 3, cell = cc & 7;
    int k0 = c * 64 + cell * 8;

    const float4* s = (const float4*)(src + (size_t)n * DD + k0);
    float4 a = s[0], b = s[1];

    uint4 H = make_uint4(pk2h(a.x,a.y), pk2h(a.z,a.w), pk2h(b.x,b.y), pk2h(b.z,b.w));
    size_t off16 = ((size_t)c * DD + n) * 8 + (cell ^ (n & 7));
    dst[off16] = H;
}

// ---------------------------------------------------------------------------
// Kernel: mma_gemm — C[8192x1024] = A @ W^T (+bias, optionally +X residual)
// fp16 single-product (fp32 accum). 4-stage cp.async.bulk pipeline, scoped
// mbarrier flow control, register double-buffered ldmatrix.
// CTA tile 128x256, 8 warps (2x4), warp tile 64x64.
// MODE 0: C = g_valh (fp16), B = Wv panel. MODE 1: C = Cout += X, B = Wo panel.
// ---------------------------------------------------------------------------
#define TILE_A   16384                  // 128x64 fp16
#define TILE_BB  32768                  // 256x64 fp16
#define STG      (TILE_A + TILE_BB)     // 48 KB
#define KBLK     16
#define NSTAGE   4
#define GSMEM    (1024 + NSTAGE*STG)    // 197632
#define NWARP    8

template<int MODE>
__global__ __launch_bounds__(256, 1)
void mma_gemm(const float* __restrict__ bias, const float* __restrict__ X,
              float* __restrict__ Cout)
{
    extern __shared__ char smem[];
    unsigned sb = smem_u32(smem);
    int tid = threadIdx.x, lane = tid & 31, wid = tid >> 5;
    int wm = wid & 1, wn = wid >> 1;          // 2 x 4 warp grid, 64x64 tiles
    int bn = blockIdx.x * 256, bm = blockIdx.y * 128;

    if (tid == 0) {
        #pragma unroll
        for (int s = 0; s < NSTAGE; ++s) {
            MBAR_INIT(sb + 8  + 16*s, 1);
            MBAR_INIT(sb + 16 + 16*s, NWARP);
        }
        FENCE_PROXY();
    }
    __syncthreads();

    const char* pA = (const char*)g_ahi;
    const char* pB = (MODE == 0) ? (const char*)g_bhi : (const char*)g_bhi2;

    auto issue = [&](int kb, int s) {
        unsigned st = sb + 1024 + s * STG;
        unsigned fm = sb + 8 + 16*s;
        size_t aoff = ((size_t)kb * BL + bm) * 128;
        size_t boff = ((size_t)kb * DD + bn) * 128;
        MBAR_EXPECT_TX(fm, STG);
        CP_BULK(st,          pA + aoff, TILE_A,  fm);
        CP_BULK(st + TILE_A, pB + boff, TILE_BB, fm);
    };
    if (tid == 0) {
        #pragma unroll
        for (int s = 0; s < NSTAGE - 1; ++s) issue(s, s);
    }

    float acc[4][8][4];
    #pragma unroll
    for (int i = 0; i < 4; ++i)
        #pragma unroll
        for (int j = 0; j < 8; ++j)
            #pragma unroll
            for (int q = 0; q < 4; ++q) acc[i][j][q] = 0.f;

    int rl = (lane & 7) + ((lane >> 3) & 1) * 8;
    int cs = lane >> 4;

    int rA[4], sA[4], rB[4], sB[4];
    #pragma unroll
    for (int i = 0; i < 4; ++i) { int r = wm*64 + i*16 + rl; rA[i] = r*128; sA[i] = r & 7; }
    #pragma unroll
    for (int j = 0; j < 4; ++j) { int r = wn*64 + j*16 + rl; rB[j] = r*128; sB[j] = r & 7; }

    unsigned opA[2][16], opB[2][16];

    auto load_ops = [&](unsigned bA, unsigned bBp, int ks, unsigned* A, unsigned* B) {
        int cc = ks * 2 + cs;
        #pragma unroll
        for (int i = 0; i < 4; ++i) {
            unsigned off = rA[i] + ((cc ^ sA[i]) << 4);
            LDSM_X4(A[i*4+0], A[i*4+1], A[i*4+2], A[i*4+3], bA + off);
        }
        #pragma unroll
        for (int j = 0; j < 4; ++j) {
            unsigned off = rB[j] + ((cc ^ sB[j]) << 4);
            unsigned r0, r1, r2, r3;
            LDSM_X4(r0, r1, r2, r3, bBp + off);
            B[j*4+0] = r0; B[j*4+1] = r2; B[j*4+2] = r1; B[j*4+3] = r3;
        }
    };

    auto do_mma = [&](const unsigned* A, const unsigned* B) {
        #pragma unroll
        for (int jt = 0; jt < 4; ++jt)
            #pragma unroll
            for (int h = 0; h < 2; ++h) {
                const unsigned* Bf = B + jt*4 + h*2;
                #pragma unroll
                for (int i = 0; i < 4; ++i)
                    mma16816h(acc[i][jt*2+h], A + i*4, Bf);
            }
    };

    for (int kb = 0; kb < KBLK; ++kb) {
        int s  = kb % NSTAGE;
        int ph = (kb / NSTAGE) & 1;
        MBAR_WAIT(sb + 8 + 16*s, ph);
        unsigned st = sb + 1024 + s * STG;
        unsigned bA = st, bBp = st + TILE_A;

        load_ops(bA, bBp, 0, opA[0], opB[0]);
        #pragma unroll
        for (int ks = 0; ks < 4; ++ks) {
            int cur = ks & 1;
            if (ks < 3) load_ops(bA, bBp, ks + 1, opA[cur^1], opB[cur^1]);
            do_mma(opA[cur], opB[cur]);
        }

        if (lane == 0) MBAR_ARRIVE(sb + 16 + 16*s);
        if (tid == 0 && kb + NSTAGE - 1 < KBLK) {
            MBAR_WAIT(sb + 16 + 16*s, ph);
            issue(kb + NSTAGE - 1, (kb + NSTAGE - 1) % NSTAGE);
        }
    }

    // epilogue: warp writes its 64x64 sub-tile
    #pragma unroll
    for (int i = 0; i < 4; ++i) {
        int r0 = bm + wm*64 + i*16 + (lane >> 2);
        #pragma unroll
        for (int j = 0; j < 8; ++j) {
            int col = bn + wn*64 + j*8 + (lane & 3)*2;
            float2 b2 = *(const float2*)(bias + col);
            float2 v0 = make_float2(acc[i][j][0] + b2.x, acc[i][j][1] + b2.y);
            float2 v1 = make_float2(acc[i][j][2] + b2.x, acc[i][j][3] + b2.y);
            if (MODE == 1) {
                float2 x0 = *(const float2*)(X + (size_t)r0*DD + col);
                float2 x1 = *(const float2*)(X + (size_t)(r0+8)*DD + col);
                v0.x += x0.x; v0.y += x0.y;
                v1.x += x1.x; v1.y += x1.y;
                *(float2*)(Cout + (size_t)r0*DD + col)     = v0;
                *(float2*)(Cout + (size_t)(r0+8)*DD + col) = v1;
            } else {
                *(__half2*)(&g_valh[(size_t)r0*DD + col])     = __floats2half2_rn(v0.x, v0.y);
                *(__half2*)(&g_valh[(size_t)(r0+8)*DD + col]) = __floats2half2_rn(v1.x, v1.y);
            }
        }
    }

    __syncthreads();
    if (tid == 0) {
        #pragma unroll
        for (int s = 0; s < NSTAGE; ++s) {
            MBAR_INVAL(sb + 8  + 16*s);
            MBAR_INVAL(sb + 16 + 16*s);
        }
    }
}

// ---------------------------------------------------------------------------
// Kernel: proj — content key/query + combiner for 8 tokens per block,
// FUSED with x -> fp16 A-panel conversion (reads x once).
// ---------------------------------------------------------------------------
#define PT 8
__global__ __launch_bounds__(256)
void proj_kernel(const float* __restrict__ x,
                 const float* __restrict__ Wck, const float* __restrict__ bck,
                 const float* __restrict__ Wcq, const float* __restrict__ bcq,
                 const float* __restrict__ Wc,  const float* __restrict__ bc,
                 const float* __restrict__ pos_key)
{
    int t0   = blockIdx.x * PT;
    int tid  = threadIdx.x;
    int lane = tid & 31;
    int warp = tid >> 5;

    __shared__ float xs[PT][DD];
    __shared__ float dots[2][PT][16];
    __shared__ float pos_s[PT][16];

    #pragma unroll
    for (int i = tid; i < PT*DD/4; i += 256)
        ((float4*)&xs[0][0])[i] = ((const float4*)(x + (size_t)t0*DD))[i];
    if (tid < PT*16) {
        int tt = tid >> 4, k = tid & 15;
        int l = (t0 + tt) & (LL-1);
        pos_s[tt][k] = pos_key[l*KK + k];
    }
    __syncthreads();

    // --- fused conv: emit fp16 panel rows ---
    {
        int tt   = tid >> 5;
        int t    = t0 + tt;
        int cell = lane & 7;
        #pragma unroll
        for (int q = 0; q < 4; ++q) {
            int c  = (lane >> 3) + q*4;
            int k0 = c*64 + cell*8;
            const float* v = &xs[tt][k0];
            uint4 H = make_uint4(pk2h(v[0],v[1]), pk2h(v[2],v[3]),
                                 pk2h(v[4],v[5]), pk2h(v[6],v[7]));
            size_t off16 = ((size_t)c * BL + t) * 8 + (cell ^ (t & 7));
            g_ahi[off16] = H;
        }
    }

    // --- 32 dot products; each warp does 4 (sequential — keeps regs low) ---
    #pragma unroll 1
    for (int oo = 0; oo < 4; ++oo) {
        int o = warp + oo*8;
        const float* W = (o < 16) ? (Wck + (size_t)o*DD) : (Wcq + (size_t)(o-16)*DD);
        float bias_o   = (o < 16) ? bck[o] : bcq[o-16];
        float wreg[32];
        #pragma unroll
        for (int i = 0; i < 32; ++i) wreg[i] = W[lane + 32*i];
        #pragma unroll
        for (int t = 0; t < PT; ++t) {
            float s = 0.f;
            #pragma unroll
            for (int i = 0; i < 32; ++i) s += wreg[i] * xs[t][lane + 32*i];
            #pragma unroll
            for (int off = 16; off; off >>= 1)
                s += __shfl_xor_sync(0xffffffffu, s, off);
            if (lane == 0)
                dots[o >> 4][t][o & 15] = s + bias_o;
        }
    }
    __syncthreads();

    // --- normalize + combiner + normalize ---
    {
        int t    = warp;
        int path = lane >> 4;
        int l16  = lane & 15;

        float v = dots[path][t][l16];
        float ss = v*v;
        #pragma unroll
        for (int off = 8; off; off >>= 1)
            ss += __shfl_xor_sync(0xffffffffu, ss, off, 16);
        float cnv = v / fmaxf(sqrtf(ss), 1e-12f);

        float s = bc[l16];
        #pragma unroll
        for (int j = 0; j < 16; ++j) {
            float cj = __shfl_sync(0xffffffffu, cnv, j, 16);
            s += Wc[l16*32 + j]      * pos_s[t][j];
            s += Wc[l16*32 + 16 + j] * cj;
        }
        s = tanhf(s);
        float sq = s*s;
        #pragma unroll
        for (int off = 8; off; off >>= 1)
            sq += __shfl_xor_sync(0xffffffffu, sq, off, 16);
        float outv = s / fmaxf(sqrtf(sq), 1e-12f);
        float* dst = (path == 0) ? g_ck : g_cq;
        dst[(t0 + t)*KK + l16] = outv;
    }
}

// ---------------------------------------------------------------------------
// Kernel: per-chunk partial state, 2 d-columns per thread, t-loop unrolled x4
// with front-batched loads. grid = (DD/256, NCH, BB), 128 threads.
// ---------------------------------------------------------------------------
__global__ __launch_bounds__(128)
void scan_partial()
{
    int d2 = blockIdx.x * 128 + threadIdx.x;   // 0..511 -> pair (2*d2, 2*d2+1)
    int c = blockIdx.y;
    int b = blockIdx.z;
    __shared__ float cks[LC*KK];

    int base_t = b*LL + c*LC;
    for (int i = threadIdx.x; i < LC*KK; i += 128)
        cks[i] = g_ck[base_t*KK + i];
    __syncthreads();

    float sx[KK], sy[KK];
    #pragma unroll
    for (int k = 0; k < KK; ++k) { sx[k] = 0.f; sy[k] = 0.f; }

    const __half2* vp = (const __half2*)(g_valh + (size_t)base_t*DD) + d2;
    #pragma unroll 1
    for (int t = 0; t < LC; t += 4) {
        float2 v[4];
        #pragma unroll
        for (int u = 0; u < 4; ++u)
            v[u] = __half22float2(vp[(size_t)(t+u)*(DD/2)]);
        #pragma unroll
        for (int u = 0; u < 4; ++u) {
            #pragma unroll
            for (int k = 0; k < KK; ++k) {
                float ckv = cks[(t+u)*KK + k];
                sx[k] += v[u].x * ckv;
                sy[k] += v[u].y * ckv;
            }
        }
    }
    float2* Sp = (float2*)(g_S + ((size_t)(b*NCH + c)*KK)*DD) + d2;
    #pragma unroll
    for (int k = 0; k < KK; ++k)
        Sp[(size_t)k*(DD/2)] = make_float2(sx[k], sy[k]);
}

// ---------------------------------------------------------------------------
// Kernel: exclusive prefix over chunks — batched loads for MLP
// ---------------------------------------------------------------------------
__global__ __launch_bounds__(256)
void scan_prefix()
{
    int id  = blockIdx.x * 256 + threadIdx.x;   // 0 .. B*K*D-1
    int b   = id >> 14;
    int rem = id & 16383;
    float* base = g_S + (size_t)b*NCH*KK*DD + rem;

    // two-half batched to bound register pressure at NCH=64
    float run = 0.f;
    #pragma unroll 1
    for (int h = 0; h < 2; ++h) {
        float v[NCH/2];
        #pragma unroll
        for (int c = 0; c < NCH/2; ++c)
            v[c] = base[(size_t)(h*(NCH/2) + c)*KK*DD];
        #pragma unroll
        for (int c = 0; c < NCH/2; ++c) {
            float t = v[c];
            base[(size_t)(h*(NCH/2) + c)*KK*DD] = run;
            run += t;
        }
    }
}

// ---------------------------------------------------------------------------
// Kernel: apply scan, 2 d-columns per thread, t-loop unrolled x4 with
// front-batched loads -> g_reth (fp16). grid = (DD/256, NCH, BB), 128 thr.
// ---------------------------------------------------------------------------
__global__ __launch_bounds__(128)
void scan_apply()
{
    int d2 = blockIdx.x * 128 + threadIdx.x;
    int c = blockIdx.y;
    int b = blockIdx.z;
    __shared__ float cks[LC*KK];
    __shared__ float cqs[LC*KK];

    int base_t = b*LL + c*LC;
    for (int i = threadIdx.x; i < LC*KK; i += 128) {
        cks[i] = g_ck[base_t*KK + i];
        cqs[i] = g_cq[base_t*KK + i];
    }
    __syncthreads();

    float sx[KK], sy[KK];
    const float2* Sp = (const float2*)(g_S + ((size_t)(b*NCH + c)*KK)*DD) + d2;
    #pragma unroll
    for (int k = 0; k < KK; ++k) {
        float2 s = Sp[(size_t)k*(DD/2)];
        sx[k] = s.x; sy[k] = s.y;
    }

    const __half2* vp = (const __half2*)(g_valh + (size_t)base_t*DD) + d2;
    __half2*       rp = (__half2*)(g_reth + (size_t)base_t*DD) + d2;
    #pragma unroll 1
    for (int t = 0; t < LC; t += 4) {
        float2 v[4];
        #pragma unroll
        for (int u = 0; u < 4; ++u)
            v[u] = __half22float2(vp[(size_t)(t+u)*(DD/2)]);
        #pragma unroll
        for (int u = 0; u < 4; ++u) {
            float ax = 0.f, ay = 0.f;
            #pragma unroll
            for (int k = 0; k < KK; ++k) {
                float ckv = cks[(t+u)*KK + k];
                float cqv = cqs[(t+u)*KK + k];
                sx[k] += v[u].x * ckv;
                sy[k] += v[u].y * ckv;
                ax    += cqv * sx[k];
                ay    += cqv * sy[k];
            }
            rp[(size_t)(t+u)*(DD/2)] = __floats2half2_rn(ax * 0.25f, ay * 0.25f);
        }
    }
}

// ---------------------------------------------------------------------------
// Kernel: LayerNorm on g_reth (fp16 in), fused fp16 panel output
// ---------------------------------------------------------------------------
__global__ __launch_bounds__(256)
void layernorm_conv(const float* __restrict__ gam, const float* __restrict__ bet)
{
    int t = blockIdx.x;
    const __half2* row = (const __half2*)(g_reth + (size_t)t*DD);
    __shared__ float sh[DD];
    __shared__ float ws[8], wq[8];
    __shared__ float s_mean, s_rstd;

    int tid  = threadIdx.x;
    int lane = tid & 31;
    int wid  = tid >> 5;

    // 256 threads * 2 half2 = 1024 values
    float2 a = __half22float2(row[tid*2]);
    float2 b = __half22float2(row[tid*2 + 1]);
    sh[tid*4+0] = a.x; sh[tid*4+1] = a.y; sh[tid*4+2] = b.x; sh[tid*4+3] = b.y;
    float s = a.x + a.y + b.x + b.y;
    float q = a.x*a.x + a.y*a.y + b.x*b.x + b.y*b.y;
    #pragma unroll
    for (int off = 16; off; off >>= 1) {
        s += __shfl_xor_sync(0xffffffffu, s, off);
        q += __shfl_xor_sync(0xffffffffu, q, off);
    }
    if (lane == 0) { ws[wid] = s; wq[wid] = q; }
    __syncthreads();
    if (tid == 0) {
        float S = 0.f, Q = 0.f;
        #pragma unroll
        for (int i = 0; i < 8; ++i) { S += ws[i]; Q += wq[i]; }
        float m   = S / (float)DD;
        float var = Q / (float)DD - m*m;
        s_mean = m;
        s_rstd = rsqrtf(var + 1e-5f);
    }
    __syncthreads();
    float m = s_mean, r = s_rstd;

    int d0 = tid * 4;
    float nv[4];
    #pragma unroll
    for (int i = 0; i < 4; ++i) {
        int d = d0 + i;
        nv[i] = (sh[d] - m) * r * gam[d] + bet[d];
    }
    int c8    = d0 >> 6;
    int inrow = ((d0 & 63) * 2) ^ ((t & 7) << 4);
    size_t byteoff = ((size_t)c8 * BL + t) * 128 + inrow;
    *(uint2*)((char*)g_ahi + byteoff) = make_uint2(pk2h(nv[0],nv[1]), pk2h(nv[2],nv[3]));
}

// ---------------------------------------------------------------------------
extern "C" void kernel_launch(void* const* d_in, const int* in_sizes, int n_in,
                              void* d_out, int out_size)
{
    const float* x       = (const float*)d_in[0];
    const float* Wv      = (const float*)d_in[1];
    const float* bv      = (const float*)d_in[2];
    const float* Wck     = (const float*)d_in[3];
    const float* bck     = (const float*)d_in[4];
    const float* Wc      = (const float*)d_in[5];
    const float* bc      = (const float*)d_in[6];
    const float* Wcq     = (const float*)d_in[7];
    const float* bcq     = (const float*)d_in[8];
    const float* ln_g    = (const float*)d_in[9];
    const float* ln_b    = (const float*)d_in[10];
    const float* Wo      = (const float*)d_in[11];
    const float* bo      = (const float*)d_in[12];
    const float* pos_key = (const float*)d_in[13];
    float* out = (float*)d_out;

    cudaFuncSetAttribute(mma_gemm<0>, cudaFuncAttributeMaxDynamicSharedMemorySize, GSMEM);
    cudaFuncSetAttribute(mma_gemm<1>, cudaFuncAttributeMaxDynamicSharedMemorySize, GSMEM);

    // both weight panels in one launch (off critical path)
    conv_w<<<2*CONVW_BLOCKS, 256>>>(Wv, Wo);

    // proj + fused x->panel conversion
    proj_kernel<<<BL/PT, 256>>>(x, Wck, bck, Wcq, bcq, Wc, bc, pos_key);

    // value = x @ Wv^T + bv  (written as fp16 into g_valh)
    mma_gemm<0><<<dim3(DD/256, BL/128), 256, GSMEM>>>(bv, nullptr, nullptr);

    // chunked causal scan (64 chunks of 32 tokens -> 2x occupancy)
    {
        dim3 grid(DD/256, NCH, BB);
        scan_partial<<<grid, 128>>>();
        scan_prefix<<<(BB*KK*DD)/256, 256>>>();
        scan_apply<<<grid, 128>>>();
    }

    // LayerNorm + fused fp16 conversion into A panel
    layernorm_conv<<<BL, 256>>>(ln_g, ln_b);

    // out = x + normed @ Wo^T + bo
    mma_gemm<1><<<dim3(DD/256, BL/128), 256, GSMEM>>>(bo, x, out);
}